// round 2
// baseline (speedup 1.0000x reference)
#include <cuda_runtime.h>
#include <math.h>

// Problem constants
constexpr int B_ = 512;
constexpr int T_ = 256;
constexpr int C_ = 384;   // n_embd
constexpr int H_ = 64;    // head_size
constexpr int BT_ = B_ * T_;          // 131072 rows
constexpr float SCALE_ = 0.05103103630798287f;  // 384^-0.5 (ref scales by n_embd)

// Scratch for Q, K, V projections (allocation-free: __device__ globals)
__device__ float g_q[(size_t)BT_ * H_];
__device__ float g_k[(size_t)BT_ * H_];
__device__ float g_v[(size_t)BT_ * H_];

// ---------------------------------------------------------------------------
// Kernel 1: fused QKV projection.
// Grid: BT_/ROWS blocks, 256 threads. Each block: 32 rows of x in SMEM,
// each thread computes 8 rows x 1 col for all three weight matrices.
// ---------------------------------------------------------------------------
constexpr int PROJ_ROWS = 32;

__global__ __launch_bounds__(256) void proj_kernel(
    const float* __restrict__ x,
    const float* __restrict__ Wq, const float* __restrict__ bq,
    const float* __restrict__ Wk, const float* __restrict__ bk,
    const float* __restrict__ Wv, const float* __restrict__ bv)
{
    __shared__ float xs[PROJ_ROWS][C_];   // 48 KB

    const int row0 = blockIdx.x * PROJ_ROWS;

    // Cooperative load of the x tile (coalesced float4)
    const float4* xg = reinterpret_cast<const float4*>(x + (size_t)row0 * C_);
    float4* xs4 = reinterpret_cast<float4*>(&xs[0][0]);
    constexpr int NV4 = PROJ_ROWS * C_ / 4;   // 3072
    for (int i = threadIdx.x; i < NV4; i += blockDim.x) xs4[i] = xg[i];
    __syncthreads();

    const int col = threadIdx.x & 63;     // 0..63 output column
    const int rg  = threadIdx.x >> 6;     // 0..3 row group (8 rows each)

    float accq[8], acck[8], accv[8];
#pragma unroll
    for (int r = 0; r < 8; r++) { accq[r] = 0.f; acck[r] = 0.f; accv[r] = 0.f; }

#pragma unroll 4
    for (int c = 0; c < C_; c++) {
        const float wq = Wq[c * H_ + col];
        const float wk = Wk[c * H_ + col];
        const float wv = Wv[c * H_ + col];
#pragma unroll
        for (int r = 0; r < 8; r++) {
            const float xv = xs[rg * 8 + r][c];   // warp-uniform row -> LDS broadcast
            accq[r] = fmaf(xv, wq, accq[r]);
            acck[r] = fmaf(xv, wk, acck[r]);
            accv[r] = fmaf(xv, wv, accv[r]);
        }
    }

    const float bqv = bq[col], bkv = bk[col], bvv = bv[col];
#pragma unroll
    for (int r = 0; r < 8; r++) {
        const size_t o = (size_t)(row0 + rg * 8 + r) * H_ + col;
        g_q[o] = accq[r] + bqv;
        g_k[o] = acck[r] + bkv;
        g_v[o] = accv[r] + bvv;
    }
}

// ---------------------------------------------------------------------------
// Kernel 2: causal flash-style attention.
// Grid: (B, T/BM). Block: BM=128 threads, one query row per thread.
// q and acc in registers, K/V 128-key tiles in SMEM, online softmax with
// conditional (max-update-only) rescale.
// ---------------------------------------------------------------------------
constexpr int ATT_BM = 128;
constexpr int ATT_BN = 128;

__global__ __launch_bounds__(ATT_BM) void attn_kernel(float* __restrict__ out)
{
    __shared__ float ks[ATT_BN][H_];   // 32 KB
    __shared__ float vs[ATT_BN][H_];   // 32 KB

    const int b  = blockIdx.x;
    const int mt = blockIdx.y;
    const int m  = mt * ATT_BM + threadIdx.x;   // query position in sequence
    const size_t base = (size_t)b * T_ * H_;

    // Load this thread's query row into registers
    float q[H_];
    {
        const float4* qg = reinterpret_cast<const float4*>(g_q + base + (size_t)m * H_);
#pragma unroll
        for (int c = 0; c < H_ / 4; c++) {
            float4 v = qg[c];
            q[4*c+0] = v.x; q[4*c+1] = v.y; q[4*c+2] = v.z; q[4*c+3] = v.w;
        }
    }

    float acc[H_];
#pragma unroll
    for (int c = 0; c < H_; c++) acc[c] = 0.f;
    float mrun = -1e30f;
    float lsum = 0.f;

    const int ntiles = mt + 1;   // causal: only key tiles <= query tile
    for (int j = 0; j < ntiles; j++) {
        // Cooperative coalesced load of K/V tile (float4, linear)
        {
            const float4* kg = reinterpret_cast<const float4*>(g_k + base + (size_t)j * ATT_BN * H_);
            const float4* vg = reinterpret_cast<const float4*>(g_v + base + (size_t)j * ATT_BN * H_);
            float4* ks4 = reinterpret_cast<float4*>(&ks[0][0]);
            float4* vs4 = reinterpret_cast<float4*>(&vs[0][0]);
            constexpr int NV4 = ATT_BN * H_ / 4;   // 2048
            for (int i = threadIdx.x; i < NV4; i += ATT_BM) {
                ks4[i] = kg[i];
                vs4[i] = vg[i];
            }
        }
        __syncthreads();

        // Keys valid for this thread in this tile
        const int send = (j < mt) ? ATT_BN : (threadIdx.x + 1);

        for (int s = 0; s < send; s++) {
            // score = scale * dot(q, k_s)  (k row broadcast from SMEM)
            float sc = 0.f;
            const float4* kk = reinterpret_cast<const float4*>(&ks[s][0]);
#pragma unroll
            for (int c = 0; c < H_ / 4; c++) {
                float4 kv = kk[c];
                sc = fmaf(q[4*c+0], kv.x, sc);
                sc = fmaf(q[4*c+1], kv.y, sc);
                sc = fmaf(q[4*c+2], kv.z, sc);
                sc = fmaf(q[4*c+3], kv.w, sc);
            }
            sc *= SCALE_;

            if (sc > mrun) {
                const float corr = __expf(mrun - sc);
                mrun = sc;
                lsum *= corr;
#pragma unroll
                for (int c = 0; c < H_; c++) acc[c] *= corr;
            }
            const float p = __expf(sc - mrun);
            lsum += p;
            const float4* vv = reinterpret_cast<const float4*>(&vs[s][0]);
#pragma unroll
            for (int c = 0; c < H_ / 4; c++) {
                float4 vval = vv[c];
                acc[4*c+0] = fmaf(p, vval.x, acc[4*c+0]);
                acc[4*c+1] = fmaf(p, vval.y, acc[4*c+1]);
                acc[4*c+2] = fmaf(p, vval.z, acc[4*c+2]);
                acc[4*c+3] = fmaf(p, vval.w, acc[4*c+3]);
            }
        }
        __syncthreads();
    }

    // Normalize and write output row (coalesced within the row via float4)
    const float inv = 1.0f / lsum;
    float4* og = reinterpret_cast<float4*>(out + base + (size_t)m * H_);
#pragma unroll
    for (int c = 0; c < H_ / 4; c++) {
        float4 v;
        v.x = acc[4*c+0] * inv;
        v.y = acc[4*c+1] * inv;
        v.z = acc[4*c+2] * inv;
        v.w = acc[4*c+3] * inv;
        og[c] = v;
    }
}

// ---------------------------------------------------------------------------
// Launch
// ---------------------------------------------------------------------------
extern "C" void kernel_launch(void* const* d_in, const int* in_sizes, int n_in,
                              void* d_out, int out_size)
{
    const float* x  = (const float*)d_in[0];
    const float* Wq = (const float*)d_in[1];
    const float* bq = (const float*)d_in[2];
    const float* Wk = (const float*)d_in[3];
    const float* bk = (const float*)d_in[4];
    const float* Wv = (const float*)d_in[5];
    const float* bv = (const float*)d_in[6];
    float* out = (float*)d_out;

    proj_kernel<<<BT_ / PROJ_ROWS, 256>>>(x, Wq, bq, Wk, bk, Wv, bv);

    dim3 grid(B_, T_ / ATT_BM);
    attn_kernel<<<grid, ATT_BM>>>(out);
}

// round 4
// speedup vs baseline: 1.4676x; 1.4676x over previous
#include <cuda_runtime.h>
#include <cuda_bf16.h>
#include <math.h>
#include <stdint.h>

// Problem constants
constexpr int B_ = 512;
constexpr int T_ = 256;
constexpr int C_ = 384;   // n_embd
constexpr int H_ = 64;    // head_size
constexpr int BT_ = B_ * T_;          // 131072 rows
constexpr float SCALE_ = 0.05103103630798287f;  // 384^-0.5

// Scratch for Q, K, V projections
__device__ float g_q[(size_t)BT_ * H_];
__device__ float g_k[(size_t)BT_ * H_];
__device__ float g_v[(size_t)BT_ * H_];

// ---------------------------------------------------------------------------
// mma.sync m16n8k16 bf16 (family-wide ISA; tcgen05 is unassemblable because
// the harness PTX target is plain sm_103)
// ---------------------------------------------------------------------------
__device__ __forceinline__ void mma16816(float* d, const uint32_t* a, const uint32_t* b)
{
    asm volatile(
        "mma.sync.aligned.m16n8k16.row.col.f32.bf16.bf16.f32 "
        "{%0,%1,%2,%3}, {%4,%5,%6,%7}, {%8,%9}, {%0,%1,%2,%3};"
        : "+f"(d[0]), "+f"(d[1]), "+f"(d[2]), "+f"(d[3])
        : "r"(a[0]), "r"(a[1]), "r"(a[2]), "r"(a[3]), "r"(b[0]), "r"(b[1]));
}

// ---------------------------------------------------------------------------
// Kernel 1: fused QKV projection via HMMA, bf16x3 split precision.
// C[131072 x 192] = x[131072 x 384] * [Wq|Wk|Wv][384 x 192] + bias.
// CTA tile 128x192, 8 warps in 2x4 (64x48 each), K chunks of 32, double-buffered.
// ---------------------------------------------------------------------------
constexpr int PM = 128;
constexpr int PN = 192;
constexpr int KC = 32;
constexpr int NCH = C_ / KC;     // 12
constexpr int RST = 40;          // padded row stride in halves (conflict-free)

// SMEM (halves): per buffer: Ahi, Alo (128x40 each), Bhi, Blo (192x40 each)
constexpr int A_SPLIT = PM * RST;        // 5120
constexpr int B_SPLIT = PN * RST;        // 7680
constexpr int BUF_HALVES = 2 * A_SPLIT + 2 * B_SPLIT;   // 25600
constexpr int SMEM_PROJ_BYTES = 2 * BUF_HALVES * 2;     // 102400

__global__ __launch_bounds__(256, 1) void proj_mma_kernel(
    const float* __restrict__ x,
    const float* __restrict__ Wq, const float* __restrict__ bq,
    const float* __restrict__ Wk, const float* __restrict__ bk,
    const float* __restrict__ Wv, const float* __restrict__ bv)
{
    extern __shared__ __align__(16) uint16_t sm[];

    const int tid = threadIdx.x;
    const int w   = tid >> 5;
    const int l   = tid & 31;
    const int wm  = w >> 2;          // 0..1  (64-row band)
    const int wn  = w & 3;           // 0..3  (48-col band)
    const int row0 = blockIdx.x * PM;

    const int lq = l >> 2;           // 0..7
    const int lr = (l & 3) * 2;      // 0,2,4,6

    float acc[4][6][4];
#pragma unroll
    for (int i = 0; i < 4; i++)
#pragma unroll
        for (int j = 0; j < 6; j++)
#pragma unroll
            for (int r = 0; r < 4; r++) acc[i][j][r] = 0.f;

    // register staging for the next chunk
    float4 ra[4];
    float  rb[6][4];

    auto loadA = [&](int ch) {
#pragma unroll
        for (int t = 0; t < 4; t++) {
            const int i = tid + t * 256;        // 0..1023
            const int r = i >> 3;
            const int q = i & 7;
            ra[t] = *reinterpret_cast<const float4*>(
                x + (size_t)(row0 + r) * C_ + ch * KC + q * 4);
        }
    };
    auto loadB = [&](int ch) {
#pragma unroll
        for (int t = 0; t < 6; t++) {
            const int i = tid + t * 256;        // 0..1535
            const int n = i >> 3;               // 0..191
            const int kq = i & 7;               // 4-k group
            const int m = n >> 6;
            const int h = n & 63;
            const float* W = (m == 0) ? Wq : (m == 1) ? Wk : Wv;
#pragma unroll
            for (int j = 0; j < 4; j++)
                rb[t][j] = W[(size_t)(ch * KC + kq * 4 + j) * H_ + h];
        }
    };
    auto cvt_store = [&](int buf) {
        uint16_t* Ahi = sm + buf * BUF_HALVES;
        uint16_t* Alo = Ahi + A_SPLIT;
        uint16_t* Bhi = sm + buf * BUF_HALVES + 2 * A_SPLIT;
        uint16_t* Blo = Bhi + B_SPLIT;
#pragma unroll
        for (int t = 0; t < 4; t++) {
            const int i = tid + t * 256;
            const int r = i >> 3;
            const int q = i & 7;
            const float f[4] = {ra[t].x, ra[t].y, ra[t].z, ra[t].w};
            uint16_t hh[4], ll[4];
#pragma unroll
            for (int j = 0; j < 4; j++) {
                __nv_bfloat16 hb = __float2bfloat16_rn(f[j]);
                hh[j] = __bfloat16_as_ushort(hb);
                ll[j] = __bfloat16_as_ushort(__float2bfloat16_rn(f[j] - __bfloat162float(hb)));
            }
            uint2 hp, lp;
            hp.x = ((uint32_t)hh[1] << 16) | hh[0];
            hp.y = ((uint32_t)hh[3] << 16) | hh[2];
            lp.x = ((uint32_t)ll[1] << 16) | ll[0];
            lp.y = ((uint32_t)ll[3] << 16) | ll[2];
            *reinterpret_cast<uint2*>(Ahi + r * RST + q * 4) = hp;
            *reinterpret_cast<uint2*>(Alo + r * RST + q * 4) = lp;
        }
#pragma unroll
        for (int t = 0; t < 6; t++) {
            const int i = tid + t * 256;
            const int n = i >> 3;
            const int kq = i & 7;
            uint16_t hh[4], ll[4];
#pragma unroll
            for (int j = 0; j < 4; j++) {
                __nv_bfloat16 hb = __float2bfloat16_rn(rb[t][j]);
                hh[j] = __bfloat16_as_ushort(hb);
                ll[j] = __bfloat16_as_ushort(__float2bfloat16_rn(rb[t][j] - __bfloat162float(hb)));
            }
            uint2 hp, lp;
            hp.x = ((uint32_t)hh[1] << 16) | hh[0];
            hp.y = ((uint32_t)hh[3] << 16) | hh[2];
            lp.x = ((uint32_t)ll[1] << 16) | ll[0];
            lp.y = ((uint32_t)ll[3] << 16) | ll[2];
            *reinterpret_cast<uint2*>(Bhi + n * RST + kq * 4) = hp;
            *reinterpret_cast<uint2*>(Blo + n * RST + kq * 4) = lp;
        }
    };
    auto compute = [&](int buf) {
        const uint16_t* Ahi = sm + buf * BUF_HALVES;
        const uint16_t* Alo = Ahi + A_SPLIT;
        const uint16_t* Bhi = sm + buf * BUF_HALVES + 2 * A_SPLIT;
        const uint16_t* Blo = Bhi + B_SPLIT;
#pragma unroll
        for (int ks = 0; ks < 2; ks++) {
            const int kk = ks * 16 + lr;
            uint32_t bh[6][2], bl[6][2];
#pragma unroll
            for (int j = 0; j < 6; j++) {
                const int n = wn * 48 + j * 8 + lq;
                bh[j][0] = *reinterpret_cast<const uint32_t*>(Bhi + n * RST + kk);
                bh[j][1] = *reinterpret_cast<const uint32_t*>(Bhi + n * RST + kk + 8);
                bl[j][0] = *reinterpret_cast<const uint32_t*>(Blo + n * RST + kk);
                bl[j][1] = *reinterpret_cast<const uint32_t*>(Blo + n * RST + kk + 8);
            }
#pragma unroll
            for (int i = 0; i < 4; i++) {
                const int r = wm * 64 + i * 16 + lq;
                uint32_t a[4];
                a[0] = *reinterpret_cast<const uint32_t*>(Ahi + r * RST + kk);
                a[1] = *reinterpret_cast<const uint32_t*>(Ahi + (r + 8) * RST + kk);
                a[2] = *reinterpret_cast<const uint32_t*>(Ahi + r * RST + kk + 8);
                a[3] = *reinterpret_cast<const uint32_t*>(Ahi + (r + 8) * RST + kk + 8);
#pragma unroll
                for (int j = 0; j < 6; j++) {
                    mma16816(acc[i][j], a, bh[j]);   // hi * hi
                    mma16816(acc[i][j], a, bl[j]);   // hi * lo
                }
            }
#pragma unroll
            for (int i = 0; i < 4; i++) {
                const int r = wm * 64 + i * 16 + lq;
                uint32_t a[4];
                a[0] = *reinterpret_cast<const uint32_t*>(Alo + r * RST + kk);
                a[1] = *reinterpret_cast<const uint32_t*>(Alo + (r + 8) * RST + kk);
                a[2] = *reinterpret_cast<const uint32_t*>(Alo + r * RST + kk + 8);
                a[3] = *reinterpret_cast<const uint32_t*>(Alo + (r + 8) * RST + kk + 8);
#pragma unroll
                for (int j = 0; j < 6; j++)
                    mma16816(acc[i][j], a, bh[j]);   // lo * hi
            }
        }
    };

    // --- pipeline ---
    loadA(0); loadB(0);
    cvt_store(0);
    __syncthreads();
    for (int ch = 0; ch < NCH; ch++) {
        const int buf = ch & 1;
        if (ch + 1 < NCH) { loadA(ch + 1); loadB(ch + 1); }
        compute(buf);
        if (ch + 1 < NCH) cvt_store(buf ^ 1);
        __syncthreads();
    }

    // --- epilogue: bias + store fp32 to g_q/g_k/g_v ---
#pragma unroll
    for (int j = 0; j < 6; j++) {
        const int n0 = wn * 48 + j * 8 + lr;
        const int mat = n0 >> 6;
        const int nn  = n0 & 63;
        float* dst = (mat == 0) ? g_q : (mat == 1) ? g_k : g_v;
        const float* bias = (mat == 0) ? bq : (mat == 1) ? bk : bv;
        const float b0 = bias[nn], b1 = bias[nn + 1];
#pragma unroll
        for (int i = 0; i < 4; i++) {
            const int r = row0 + wm * 64 + i * 16 + lq;
            float2 o0, o1;
            o0.x = acc[i][j][0] + b0;
            o0.y = acc[i][j][1] + b1;
            o1.x = acc[i][j][2] + b0;
            o1.y = acc[i][j][3] + b1;
            *reinterpret_cast<float2*>(dst + (size_t)r * H_ + nn) = o0;
            *reinterpret_cast<float2*>(dst + (size_t)(r + 8) * H_ + nn) = o1;
        }
    }
}

// ---------------------------------------------------------------------------
// Kernel 2: causal flash-style attention (scalar fp32, 2-key unrolled).
// ---------------------------------------------------------------------------
constexpr int ATT_BM = 128;
constexpr int ATT_BN = 128;

__global__ __launch_bounds__(ATT_BM) void attn_kernel(float* __restrict__ out)
{
    __shared__ float ks[ATT_BN][H_];
    __shared__ float vs[ATT_BN][H_];

    const int b  = blockIdx.x;
    const int mt = blockIdx.y;
    const int m  = mt * ATT_BM + threadIdx.x;
    const size_t base = (size_t)b * T_ * H_;

    float q[H_];
    {
        const float4* qg = reinterpret_cast<const float4*>(g_q + base + (size_t)m * H_);
#pragma unroll
        for (int c = 0; c < H_ / 4; c++) {
            float4 v = qg[c];
            q[4*c+0] = v.x; q[4*c+1] = v.y; q[4*c+2] = v.z; q[4*c+3] = v.w;
        }
    }

    float acc[H_];
#pragma unroll
    for (int c = 0; c < H_; c++) acc[c] = 0.f;
    float mrun = -1e30f;
    float lsum = 0.f;

    const int ntiles = mt + 1;
    for (int j = 0; j < ntiles; j++) {
        {
            const float4* kg = reinterpret_cast<const float4*>(g_k + base + (size_t)j * ATT_BN * H_);
            const float4* vg = reinterpret_cast<const float4*>(g_v + base + (size_t)j * ATT_BN * H_);
            float4* ks4 = reinterpret_cast<float4*>(&ks[0][0]);
            float4* vs4 = reinterpret_cast<float4*>(&vs[0][0]);
            constexpr int NV4 = ATT_BN * H_ / 4;
            for (int i = threadIdx.x; i < NV4; i += ATT_BM) {
                ks4[i] = kg[i];
                vs4[i] = vg[i];
            }
        }
        __syncthreads();

        const int send = (j < mt) ? ATT_BN : (threadIdx.x + 1);

        int s = 0;
        for (; s + 2 <= send; s += 2) {
            float a0 = 0.f, b0 = 0.f, a1 = 0.f, b1 = 0.f;
            const float4* k0 = reinterpret_cast<const float4*>(&ks[s][0]);
            const float4* k1 = reinterpret_cast<const float4*>(&ks[s + 1][0]);
#pragma unroll
            for (int c = 0; c < H_ / 4; c += 2) {
                float4 kva = k0[c],     kvb = k0[c + 1];
                float4 kwa = k1[c],     kwb = k1[c + 1];
                a0 = fmaf(q[4*c+0], kva.x, a0); a0 = fmaf(q[4*c+1], kva.y, a0);
                a0 = fmaf(q[4*c+2], kva.z, a0); a0 = fmaf(q[4*c+3], kva.w, a0);
                b0 = fmaf(q[4*c+4], kvb.x, b0); b0 = fmaf(q[4*c+5], kvb.y, b0);
                b0 = fmaf(q[4*c+6], kvb.z, b0); b0 = fmaf(q[4*c+7], kvb.w, b0);
                a1 = fmaf(q[4*c+0], kwa.x, a1); a1 = fmaf(q[4*c+1], kwa.y, a1);
                a1 = fmaf(q[4*c+2], kwa.z, a1); a1 = fmaf(q[4*c+3], kwa.w, a1);
                b1 = fmaf(q[4*c+4], kwb.x, b1); b1 = fmaf(q[4*c+5], kwb.y, b1);
                b1 = fmaf(q[4*c+6], kwb.z, b1); b1 = fmaf(q[4*c+7], kwb.w, b1);
            }
            const float sc0 = (a0 + b0) * SCALE_;
            const float sc1 = (a1 + b1) * SCALE_;
            const float nm = fmaxf(mrun, fmaxf(sc0, sc1));
            if (nm > mrun) {
                const float corr = __expf(mrun - nm);
                mrun = nm;
                lsum *= corr;
#pragma unroll
                for (int c = 0; c < H_; c++) acc[c] *= corr;
            }
            const float p0 = __expf(sc0 - mrun);
            const float p1 = __expf(sc1 - mrun);
            lsum += p0 + p1;
            const float4* v0 = reinterpret_cast<const float4*>(&vs[s][0]);
            const float4* v1 = reinterpret_cast<const float4*>(&vs[s + 1][0]);
#pragma unroll
            for (int c = 0; c < H_ / 4; c++) {
                float4 va = v0[c], vb = v1[c];
                acc[4*c+0] = fmaf(p0, va.x, acc[4*c+0]);
                acc[4*c+1] = fmaf(p0, va.y, acc[4*c+1]);
                acc[4*c+2] = fmaf(p0, va.z, acc[4*c+2]);
                acc[4*c+3] = fmaf(p0, va.w, acc[4*c+3]);
                acc[4*c+0] = fmaf(p1, vb.x, acc[4*c+0]);
                acc[4*c+1] = fmaf(p1, vb.y, acc[4*c+1]);
                acc[4*c+2] = fmaf(p1, vb.z, acc[4*c+2]);
                acc[4*c+3] = fmaf(p1, vb.w, acc[4*c+3]);
            }
        }
        if (s < send) {
            float a0 = 0.f, b0 = 0.f;
            const float4* kk = reinterpret_cast<const float4*>(&ks[s][0]);
#pragma unroll
            for (int c = 0; c < H_ / 4; c += 2) {
                float4 kva = kk[c], kvb = kk[c + 1];
                a0 = fmaf(q[4*c+0], kva.x, a0); a0 = fmaf(q[4*c+1], kva.y, a0);
                a0 = fmaf(q[4*c+2], kva.z, a0); a0 = fmaf(q[4*c+3], kva.w, a0);
                b0 = fmaf(q[4*c+4], kvb.x, b0); b0 = fmaf(q[4*c+5], kvb.y, b0);
                b0 = fmaf(q[4*c+6], kvb.z, b0); b0 = fmaf(q[4*c+7], kvb.w, b0);
            }
            const float sc = (a0 + b0) * SCALE_;
            if (sc > mrun) {
                const float corr = __expf(mrun - sc);
                mrun = sc;
                lsum *= corr;
#pragma unroll
                for (int c = 0; c < H_; c++) acc[c] *= corr;
            }
            const float p = __expf(sc - mrun);
            lsum += p;
            const float4* vv = reinterpret_cast<const float4*>(&vs[s][0]);
#pragma unroll
            for (int c = 0; c < H_ / 4; c++) {
                float4 vval = vv[c];
                acc[4*c+0] = fmaf(p, vval.x, acc[4*c+0]);
                acc[4*c+1] = fmaf(p, vval.y, acc[4*c+1]);
                acc[4*c+2] = fmaf(p, vval.z, acc[4*c+2]);
                acc[4*c+3] = fmaf(p, vval.w, acc[4*c+3]);
            }
        }
        __syncthreads();
    }

    const float inv = 1.0f / lsum;
    float4* og = reinterpret_cast<float4*>(out + base + (size_t)m * H_);
#pragma unroll
    for (int c = 0; c < H_ / 4; c++) {
        float4 v;
        v.x = acc[4*c+0] * inv;
        v.y = acc[4*c+1] * inv;
        v.z = acc[4*c+2] * inv;
        v.w = acc[4*c+3] * inv;
        og[c] = v;
    }
}

// ---------------------------------------------------------------------------
// Launch
// ---------------------------------------------------------------------------
extern "C" void kernel_launch(void* const* d_in, const int* in_sizes, int n_in,
                              void* d_out, int out_size)
{
    const float* x  = (const float*)d_in[0];
    const float* Wq = (const float*)d_in[1];
    const float* bq = (const float*)d_in[2];
    const float* Wk = (const float*)d_in[3];
    const float* bk = (const float*)d_in[4];
    const float* Wv = (const float*)d_in[5];
    const float* bv = (const float*)d_in[6];
    float* out = (float*)d_out;

    static bool attr_set = false;
    if (!attr_set) {
        cudaFuncSetAttribute(proj_mma_kernel,
                             cudaFuncAttributeMaxDynamicSharedMemorySize, SMEM_PROJ_BYTES);
        attr_set = true;
    }

    proj_mma_kernel<<<BT_ / PM, 256, SMEM_PROJ_BYTES>>>(x, Wq, bq, Wk, bk, Wv, bv);

    dim3 grid(B_, T_ / ATT_BM);
    attn_kernel<<<grid, ATT_BM>>>(out);
}

// round 5
// speedup vs baseline: 2.2632x; 1.5421x over previous
#include <cuda_runtime.h>
#include <cuda_bf16.h>
#include <cuda_fp16.h>
#include <math.h>
#include <stdint.h>

// Problem constants
constexpr int B_ = 512;
constexpr int T_ = 256;
constexpr int C_ = 384;   // n_embd
constexpr int H_ = 64;    // head_size
constexpr int BT_ = B_ * T_;          // 131072 rows
constexpr float SCALE_ = 0.05103103630798287f;  // 384^-0.5

// Scratch for Q, K, V projections
__device__ float g_q[(size_t)BT_ * H_];
__device__ float g_k[(size_t)BT_ * H_];
__device__ float g_v[(size_t)BT_ * H_];

// ---------------------------------------------------------------------------
// mma.sync helpers (family-wide ISA; tcgen05 unassemblable at sm_103 target)
// ---------------------------------------------------------------------------
__device__ __forceinline__ void mma_bf16(float* d, const uint32_t* a, const uint32_t* b)
{
    asm volatile(
        "mma.sync.aligned.m16n8k16.row.col.f32.bf16.bf16.f32 "
        "{%0,%1,%2,%3}, {%4,%5,%6,%7}, {%8,%9}, {%0,%1,%2,%3};"
        : "+f"(d[0]), "+f"(d[1]), "+f"(d[2]), "+f"(d[3])
        : "r"(a[0]), "r"(a[1]), "r"(a[2]), "r"(a[3]), "r"(b[0]), "r"(b[1]));
}
__device__ __forceinline__ void mma_fp16(float* d, const uint32_t* a, const uint32_t* b)
{
    asm volatile(
        "mma.sync.aligned.m16n8k16.row.col.f32.f16.f16.f32 "
        "{%0,%1,%2,%3}, {%4,%5,%6,%7}, {%8,%9}, {%0,%1,%2,%3};"
        : "+f"(d[0]), "+f"(d[1]), "+f"(d[2]), "+f"(d[3])
        : "r"(a[0]), "r"(a[1]), "r"(a[2]), "r"(a[3]), "r"(b[0]), "r"(b[1]));
}
__device__ __forceinline__ void ldmx4t(uint32_t& r0, uint32_t& r1, uint32_t& r2, uint32_t& r3,
                                       uint32_t addr)
{
    asm volatile("ldmatrix.sync.aligned.m8n8.x4.trans.shared.b16 {%0,%1,%2,%3}, [%4];"
                 : "=r"(r0), "=r"(r1), "=r"(r2), "=r"(r3) : "r"(addr));
}
__device__ __forceinline__ uint32_t smem_u32(const void* p) {
    uint32_t a;
    asm("{ .reg .u64 t; cvta.to.shared.u64 t, %1; cvt.u32.u64 %0, t; }" : "=r"(a) : "l"(p));
    return a;
}
__device__ __forceinline__ uint32_t pack_bf16(float a, float b) {
    return ((uint32_t)__bfloat16_as_ushort(__float2bfloat16_rn(b)) << 16) |
            (uint32_t)__bfloat16_as_ushort(__float2bfloat16_rn(a));
}
__device__ __forceinline__ uint32_t pack_fp16(float a, float b) {
    return ((uint32_t)__half_as_ushort(__float2half_rn(b)) << 16) |
            (uint32_t)__half_as_ushort(__float2half_rn(a));
}

// ---------------------------------------------------------------------------
// Kernel 1: fused QKV projection via HMMA, bf16x3 split precision. (unchanged)
// ---------------------------------------------------------------------------
constexpr int PM = 128;
constexpr int PN = 192;
constexpr int KC = 32;
constexpr int NCH = C_ / KC;     // 12
constexpr int RST = 40;

constexpr int A_SPLIT = PM * RST;
constexpr int B_SPLIT = PN * RST;
constexpr int BUF_HALVES = 2 * A_SPLIT + 2 * B_SPLIT;
constexpr int SMEM_PROJ_BYTES = 2 * BUF_HALVES * 2;     // 102400

__global__ __launch_bounds__(256, 1) void proj_mma_kernel(
    const float* __restrict__ x,
    const float* __restrict__ Wq, const float* __restrict__ bq,
    const float* __restrict__ Wk, const float* __restrict__ bk,
    const float* __restrict__ Wv, const float* __restrict__ bv)
{
    extern __shared__ __align__(16) uint16_t sm[];

    const int tid = threadIdx.x;
    const int w   = tid >> 5;
    const int l   = tid & 31;
    const int wm  = w >> 2;
    const int wn  = w & 3;
    const int row0 = blockIdx.x * PM;

    const int lq = l >> 2;
    const int lr = (l & 3) * 2;

    float acc[4][6][4];
#pragma unroll
    for (int i = 0; i < 4; i++)
#pragma unroll
        for (int j = 0; j < 6; j++)
#pragma unroll
            for (int r = 0; r < 4; r++) acc[i][j][r] = 0.f;

    float4 ra[4];
    float  rb[6][4];

    auto loadA = [&](int ch) {
#pragma unroll
        for (int t = 0; t < 4; t++) {
            const int i = tid + t * 256;
            const int r = i >> 3;
            const int q = i & 7;
            ra[t] = *reinterpret_cast<const float4*>(
                x + (size_t)(row0 + r) * C_ + ch * KC + q * 4);
        }
    };
    auto loadB = [&](int ch) {
#pragma unroll
        for (int t = 0; t < 6; t++) {
            const int i = tid + t * 256;
            const int n = i >> 3;
            const int kq = i & 7;
            const int m = n >> 6;
            const int h = n & 63;
            const float* W = (m == 0) ? Wq : (m == 1) ? Wk : Wv;
#pragma unroll
            for (int j = 0; j < 4; j++)
                rb[t][j] = W[(size_t)(ch * KC + kq * 4 + j) * H_ + h];
        }
    };
    auto cvt_store = [&](int buf) {
        uint16_t* Ahi = sm + buf * BUF_HALVES;
        uint16_t* Alo = Ahi + A_SPLIT;
        uint16_t* Bhi = sm + buf * BUF_HALVES + 2 * A_SPLIT;
        uint16_t* Blo = Bhi + B_SPLIT;
#pragma unroll
        for (int t = 0; t < 4; t++) {
            const int i = tid + t * 256;
            const int r = i >> 3;
            const int q = i & 7;
            const float f[4] = {ra[t].x, ra[t].y, ra[t].z, ra[t].w};
            uint16_t hh[4], ll[4];
#pragma unroll
            for (int j = 0; j < 4; j++) {
                __nv_bfloat16 hb = __float2bfloat16_rn(f[j]);
                hh[j] = __bfloat16_as_ushort(hb);
                ll[j] = __bfloat16_as_ushort(__float2bfloat16_rn(f[j] - __bfloat162float(hb)));
            }
            uint2 hp, lp;
            hp.x = ((uint32_t)hh[1] << 16) | hh[0];
            hp.y = ((uint32_t)hh[3] << 16) | hh[2];
            lp.x = ((uint32_t)ll[1] << 16) | ll[0];
            lp.y = ((uint32_t)ll[3] << 16) | ll[2];
            *reinterpret_cast<uint2*>(Ahi + r * RST + q * 4) = hp;
            *reinterpret_cast<uint2*>(Alo + r * RST + q * 4) = lp;
        }
#pragma unroll
        for (int t = 0; t < 6; t++) {
            const int i = tid + t * 256;
            const int n = i >> 3;
            const int kq = i & 7;
            uint16_t hh[4], ll[4];
#pragma unroll
            for (int j = 0; j < 4; j++) {
                __nv_bfloat16 hb = __float2bfloat16_rn(rb[t][j]);
                hh[j] = __bfloat16_as_ushort(hb);
                ll[j] = __bfloat16_as_ushort(__float2bfloat16_rn(rb[t][j] - __bfloat162float(hb)));
            }
            uint2 hp, lp;
            hp.x = ((uint32_t)hh[1] << 16) | hh[0];
            hp.y = ((uint32_t)hh[3] << 16) | hh[2];
            lp.x = ((uint32_t)ll[1] << 16) | ll[0];
            lp.y = ((uint32_t)ll[3] << 16) | ll[2];
            *reinterpret_cast<uint2*>(Bhi + n * RST + kq * 4) = hp;
            *reinterpret_cast<uint2*>(Blo + n * RST + kq * 4) = lp;
        }
    };
    auto compute = [&](int buf) {
        const uint16_t* Ahi = sm + buf * BUF_HALVES;
        const uint16_t* Alo = Ahi + A_SPLIT;
        const uint16_t* Bhi = sm + buf * BUF_HALVES + 2 * A_SPLIT;
        const uint16_t* Blo = Bhi + B_SPLIT;
#pragma unroll
        for (int ks = 0; ks < 2; ks++) {
            const int kk = ks * 16 + lr;
            uint32_t bh[6][2], bl[6][2];
#pragma unroll
            for (int j = 0; j < 6; j++) {
                const int n = wn * 48 + j * 8 + lq;
                bh[j][0] = *reinterpret_cast<const uint32_t*>(Bhi + n * RST + kk);
                bh[j][1] = *reinterpret_cast<const uint32_t*>(Bhi + n * RST + kk + 8);
                bl[j][0] = *reinterpret_cast<const uint32_t*>(Blo + n * RST + kk);
                bl[j][1] = *reinterpret_cast<const uint32_t*>(Blo + n * RST + kk + 8);
            }
#pragma unroll
            for (int i = 0; i < 4; i++) {
                const int r = wm * 64 + i * 16 + lq;
                uint32_t a[4];
                a[0] = *reinterpret_cast<const uint32_t*>(Ahi + r * RST + kk);
                a[1] = *reinterpret_cast<const uint32_t*>(Ahi + (r + 8) * RST + kk);
                a[2] = *reinterpret_cast<const uint32_t*>(Ahi + r * RST + kk + 8);
                a[3] = *reinterpret_cast<const uint32_t*>(Ahi + (r + 8) * RST + kk + 8);
#pragma unroll
                for (int j = 0; j < 6; j++) {
                    mma_bf16(acc[i][j], a, bh[j]);
                    mma_bf16(acc[i][j], a, bl[j]);
                }
            }
#pragma unroll
            for (int i = 0; i < 4; i++) {
                const int r = wm * 64 + i * 16 + lq;
                uint32_t a[4];
                a[0] = *reinterpret_cast<const uint32_t*>(Alo + r * RST + kk);
                a[1] = *reinterpret_cast<const uint32_t*>(Alo + (r + 8) * RST + kk);
                a[2] = *reinterpret_cast<const uint32_t*>(Alo + r * RST + kk + 8);
                a[3] = *reinterpret_cast<const uint32_t*>(Alo + (r + 8) * RST + kk + 8);
#pragma unroll
                for (int j = 0; j < 6; j++)
                    mma_bf16(acc[i][j], a, bh[j]);
            }
        }
    };

    loadA(0); loadB(0);
    cvt_store(0);
    __syncthreads();
    for (int ch = 0; ch < NCH; ch++) {
        const int buf = ch & 1;
        if (ch + 1 < NCH) { loadA(ch + 1); loadB(ch + 1); }
        compute(buf);
        if (ch + 1 < NCH) cvt_store(buf ^ 1);
        __syncthreads();
    }

#pragma unroll
    for (int j = 0; j < 6; j++) {
        const int n0 = wn * 48 + j * 8 + lr;
        const int mat = n0 >> 6;
        const int nn  = n0 & 63;
        float* dst = (mat == 0) ? g_q : (mat == 1) ? g_k : g_v;
        const float* bias = (mat == 0) ? bq : (mat == 1) ? bk : bv;
        const float b0 = bias[nn], b1 = bias[nn + 1];
#pragma unroll
        for (int i = 0; i < 4; i++) {
            const int r = row0 + wm * 64 + i * 16 + lq;
            float2 o0, o1;
            o0.x = acc[i][j][0] + b0;
            o0.y = acc[i][j][1] + b1;
            o1.x = acc[i][j][2] + b0;
            o1.y = acc[i][j][3] + b1;
            *reinterpret_cast<float2*>(dst + (size_t)r * H_ + nn) = o0;
            *reinterpret_cast<float2*>(dst + (size_t)(r + 8) * H_ + nn) = o1;
        }
    }
}

// ---------------------------------------------------------------------------
// Kernel 2: flash attention on mma.sync.
// CTA: 128 queries (8 warps x 16 rows), key tiles of 64.
// QK^T: bf16 3-term split. P: fp16. V: fp16 hi+lo. O accum fp32 fragments.
// ---------------------------------------------------------------------------
constexpr int ABM = 128;
constexpr int ABN = 64;
constexpr int KVR = 72;    // padded row stride (halves): 36 banks -> conflict-free

__global__ __launch_bounds__(256, 1) void attn_mma_kernel(float* __restrict__ out)
{
    __shared__ __align__(16) uint16_t KsHi[ABN * KVR];
    __shared__ __align__(16) uint16_t KsLo[ABN * KVR];
    __shared__ __align__(16) uint16_t VsHi[ABN * KVR];
    __shared__ __align__(16) uint16_t VsLo[ABN * KVR];

    const int tid = threadIdx.x;
    const int w   = tid >> 5;
    const int l   = tid & 31;
    const int lq  = l >> 2;          // 0..7
    const int lr  = (l & 3) * 2;     // 0,2,4,6

    const int bb  = blockIdx.x;
    const int mt  = blockIdx.y;
    const int q0  = mt * ABM + w * 16;         // warp's first query row
    const size_t base = (size_t)bb * T_ * H_;

    // ---- load Q fragments (scale folded in), bf16 hi/lo ----
    uint32_t qh[4][4], ql[4][4];
#pragma unroll
    for (int kt = 0; kt < 4; kt++) {
#pragma unroll
        for (int half = 0; half < 2; half++) {     // k-offset 0 / +8
            const int d = kt * 16 + lr + half * 8;
#pragma unroll
            for (int rh = 0; rh < 2; rh++) {       // row lq / lq+8
                const int r = q0 + lq + rh * 8;
                float2 v = *reinterpret_cast<const float2*>(g_q + base + (size_t)r * H_ + d);
                v.x *= SCALE_; v.y *= SCALE_;
                __nv_bfloat16 hx = __float2bfloat16_rn(v.x);
                __nv_bfloat16 hy = __float2bfloat16_rn(v.y);
                const int ri = rh + half * 2;      // a-frag register index
                qh[kt][ri] = ((uint32_t)__bfloat16_as_ushort(hy) << 16) |
                              (uint32_t)__bfloat16_as_ushort(hx);
                ql[kt][ri] = pack_bf16(v.x - __bfloat162float(hx),
                                       v.y - __bfloat162float(hy));
            }
        }
    }

    float o[8][4];
#pragma unroll
    for (int n = 0; n < 8; n++)
#pragma unroll
        for (int r = 0; r < 4; r++) o[n][r] = 0.f;
    float mrow[2] = {-1e30f, -1e30f};
    float lrow[2] = {0.f, 0.f};

    const uint32_t ksHiA = smem_u32(KsHi);
    const uint32_t ksLoA = smem_u32(KsLo);
    const uint32_t vsHiA = smem_u32(VsHi);
    const uint32_t vsLoA = smem_u32(VsLo);

    const int ntiles = 2 * mt + 2;     // key tiles covering rows < (mt+1)*128
    for (int j = 0; j < ntiles; j++) {
        __syncthreads();   // everyone done reading previous tile
        // ---- stage K/V tile: fp32 -> split halves ----
#pragma unroll
        for (int t = 0; t < 4; t++) {
            const int i = tid + t * 256;
            const int key = i >> 4;
            const int dq  = i & 15;
            const float4 kv = *reinterpret_cast<const float4*>(
                g_k + base + (size_t)(j * ABN + key) * H_ + dq * 4);
            const float kf[4] = {kv.x, kv.y, kv.z, kv.w};
            uint2 hp, lp;
            {
                uint16_t hh[4], ll[4];
#pragma unroll
                for (int e = 0; e < 4; e++) {
                    __nv_bfloat16 hb = __float2bfloat16_rn(kf[e]);
                    hh[e] = __bfloat16_as_ushort(hb);
                    ll[e] = __bfloat16_as_ushort(__float2bfloat16_rn(kf[e] - __bfloat162float(hb)));
                }
                hp.x = ((uint32_t)hh[1] << 16) | hh[0];
                hp.y = ((uint32_t)hh[3] << 16) | hh[2];
                lp.x = ((uint32_t)ll[1] << 16) | ll[0];
                lp.y = ((uint32_t)ll[3] << 16) | ll[2];
            }
            *reinterpret_cast<uint2*>(KsHi + key * KVR + dq * 4) = hp;
            *reinterpret_cast<uint2*>(KsLo + key * KVR + dq * 4) = lp;

            const float4 vv = *reinterpret_cast<const float4*>(
                g_v + base + (size_t)(j * ABN + key) * H_ + dq * 4);
            const float vf[4] = {vv.x, vv.y, vv.z, vv.w};
            {
                uint16_t hh[4], ll[4];
#pragma unroll
                for (int e = 0; e < 4; e++) {
                    __half hb = __float2half_rn(vf[e]);
                    hh[e] = __half_as_ushort(hb);
                    ll[e] = __half_as_ushort(__float2half_rn(vf[e] - __half2float(hb)));
                }
                hp.x = ((uint32_t)hh[1] << 16) | hh[0];
                hp.y = ((uint32_t)hh[3] << 16) | hh[2];
                lp.x = ((uint32_t)ll[1] << 16) | ll[0];
                lp.y = ((uint32_t)ll[3] << 16) | ll[2];
            }
            *reinterpret_cast<uint2*>(VsHi + key * KVR + dq * 4) = hp;
            *reinterpret_cast<uint2*>(VsLo + key * KVR + dq * 4) = lp;
        }
        __syncthreads();

        if (j * ABN > q0 + 15) continue;   // tile fully masked for this warp

        // ---- scores S[16, 64] ----
        float c[8][4];
#pragma unroll
        for (int nt = 0; nt < 8; nt++) {
#pragma unroll
            for (int r = 0; r < 4; r++) c[nt][r] = 0.f;
            const uint16_t* krow = KsHi + (nt * 8 + lq) * KVR;
            const uint16_t* krowL = KsLo + (nt * 8 + lq) * KVR;
#pragma unroll
            for (int kt = 0; kt < 4; kt++) {
                uint32_t bh[2], bl[2];
                bh[0] = *reinterpret_cast<const uint32_t*>(krow + kt * 16 + lr);
                bh[1] = *reinterpret_cast<const uint32_t*>(krow + kt * 16 + lr + 8);
                bl[0] = *reinterpret_cast<const uint32_t*>(krowL + kt * 16 + lr);
                bl[1] = *reinterpret_cast<const uint32_t*>(krowL + kt * 16 + lr + 8);
                mma_bf16(c[nt], qh[kt], bh);
                mma_bf16(c[nt], qh[kt], bl);
                mma_bf16(c[nt], ql[kt], bh);
            }
        }

        // ---- causal mask ----
        const bool need_mask = (j * ABN + ABN - 1) > q0;
        if (need_mask) {
#pragma unroll
            for (int nt = 0; nt < 8; nt++) {
                const int col = j * ABN + nt * 8 + lr;
                const int r0 = q0 + lq, r1 = q0 + lq + 8;
                if (col > r0)     c[nt][0] = -1e30f;
                if (col + 1 > r0) c[nt][1] = -1e30f;
                if (col > r1)     c[nt][2] = -1e30f;
                if (col + 1 > r1) c[nt][3] = -1e30f;
            }
        }

        // ---- online softmax ----
        float tm0 = -1e30f, tm1 = -1e30f;
#pragma unroll
        for (int nt = 0; nt < 8; nt++) {
            tm0 = fmaxf(tm0, fmaxf(c[nt][0], c[nt][1]));
            tm1 = fmaxf(tm1, fmaxf(c[nt][2], c[nt][3]));
        }
        tm0 = fmaxf(tm0, __shfl_xor_sync(0xffffffffu, tm0, 1));
        tm0 = fmaxf(tm0, __shfl_xor_sync(0xffffffffu, tm0, 2));
        tm1 = fmaxf(tm1, __shfl_xor_sync(0xffffffffu, tm1, 1));
        tm1 = fmaxf(tm1, __shfl_xor_sync(0xffffffffu, tm1, 2));

        const float mn0 = fmaxf(mrow[0], tm0);
        const float mn1 = fmaxf(mrow[1], tm1);
        const float corr0 = __expf(mrow[0] - mn0);
        const float corr1 = __expf(mrow[1] - mn1);
        mrow[0] = mn0; mrow[1] = mn1;

        float s0 = 0.f, s1 = 0.f;
#pragma unroll
        for (int nt = 0; nt < 8; nt++) {
            c[nt][0] = __expf(c[nt][0] - mn0);
            c[nt][1] = __expf(c[nt][1] - mn0);
            c[nt][2] = __expf(c[nt][2] - mn1);
            c[nt][3] = __expf(c[nt][3] - mn1);
            s0 += c[nt][0] + c[nt][1];
            s1 += c[nt][2] + c[nt][3];
        }
        s0 += __shfl_xor_sync(0xffffffffu, s0, 1);
        s0 += __shfl_xor_sync(0xffffffffu, s0, 2);
        s1 += __shfl_xor_sync(0xffffffffu, s1, 1);
        s1 += __shfl_xor_sync(0xffffffffu, s1, 2);
        lrow[0] = lrow[0] * corr0 + s0;
        lrow[1] = lrow[1] * corr1 + s1;

#pragma unroll
        for (int n = 0; n < 8; n++) {
            o[n][0] *= corr0; o[n][1] *= corr0;
            o[n][2] *= corr1; o[n][3] *= corr1;
        }

        // ---- P fragments (fp16) ----
        uint32_t pf[4][4];
#pragma unroll
        for (int kt = 0; kt < 4; kt++) {
            pf[kt][0] = pack_fp16(c[2*kt][0],   c[2*kt][1]);
            pf[kt][1] = pack_fp16(c[2*kt][2],   c[2*kt][3]);
            pf[kt][2] = pack_fp16(c[2*kt+1][0], c[2*kt+1][1]);
            pf[kt][3] = pack_fp16(c[2*kt+1][2], c[2*kt+1][3]);
        }

        // ---- PV: O += P * (Vhi + Vlo) via ldmatrix.x4.trans ----
        const int lm = l >> 3;                 // matrix select 0..3
        const int lrw = l & 7;                 // row within matrix
#pragma unroll
        for (int kt = 0; kt < 4; kt++) {
#pragma unroll
            for (int dp = 0; dp < 4; dp++) {
                const uint32_t off =
                    (uint32_t)((kt * 16 + (lm & 1) * 8 + lrw) * KVR + dp * 16 + (lm >> 1) * 8) * 2u;
                uint32_t b0, b1, b2, b3;
                ldmx4t(b0, b1, b2, b3, vsHiA + off);
                uint32_t bA[2] = {b0, b1};
                uint32_t bB[2] = {b2, b3};
                mma_fp16(o[2*dp],     pf[kt], bA);
                mma_fp16(o[2*dp + 1], pf[kt], bB);
                ldmx4t(b0, b1, b2, b3, vsLoA + off);
                uint32_t bC[2] = {b0, b1};
                uint32_t bD[2] = {b2, b3};
                mma_fp16(o[2*dp],     pf[kt], bC);
                mma_fp16(o[2*dp + 1], pf[kt], bD);
            }
        }
    }

    // ---- epilogue ----
    const float inv0 = 1.f / lrow[0];
    const float inv1 = 1.f / lrow[1];
    const int r0 = q0 + lq, r1 = q0 + lq + 8;
#pragma unroll
    for (int nt = 0; nt < 8; nt++) {
        float2 v0, v1;
        v0.x = o[nt][0] * inv0; v0.y = o[nt][1] * inv0;
        v1.x = o[nt][2] * inv1; v1.y = o[nt][3] * inv1;
        *reinterpret_cast<float2*>(out + base + (size_t)r0 * H_ + nt * 8 + lr) = v0;
        *reinterpret_cast<float2*>(out + base + (size_t)r1 * H_ + nt * 8 + lr) = v1;
    }
}

// ---------------------------------------------------------------------------
// Launch
// ---------------------------------------------------------------------------
extern "C" void kernel_launch(void* const* d_in, const int* in_sizes, int n_in,
                              void* d_out, int out_size)
{
    const float* x  = (const float*)d_in[0];
    const float* Wq = (const float*)d_in[1];
    const float* bq = (const float*)d_in[2];
    const float* Wk = (const float*)d_in[3];
    const float* bk = (const float*)d_in[4];
    const float* Wv = (const float*)d_in[5];
    const float* bv = (const float*)d_in[6];
    float* out = (float*)d_out;

    static bool attr_set = false;
    if (!attr_set) {
        cudaFuncSetAttribute(proj_mma_kernel,
                             cudaFuncAttributeMaxDynamicSharedMemorySize, SMEM_PROJ_BYTES);
        attr_set = true;
    }

    proj_mma_kernel<<<BT_ / PM, 256, SMEM_PROJ_BYTES>>>(x, Wq, bq, Wk, bk, Wv, bv);

    dim3 grid(B_, T_ / ABM);
    attn_mma_kernel<<<grid, 256>>>(out);
}

// round 6
// speedup vs baseline: 2.8201x; 1.2461x over previous
#include <cuda_runtime.h>
#include <cuda_bf16.h>
#include <cuda_fp16.h>
#include <math.h>
#include <stdint.h>

// Problem constants
constexpr int B_ = 512;
constexpr int T_ = 256;
constexpr int C_ = 384;   // n_embd
constexpr int H_ = 64;    // head_size
constexpr int BT_ = B_ * T_;          // 131072 rows
constexpr float SCALE_ = 0.05103103630798287f;  // 384^-0.5

// Scratch for Q, K, V projections
__device__ float g_q[(size_t)BT_ * H_];
__device__ float g_k[(size_t)BT_ * H_];
__device__ float g_v[(size_t)BT_ * H_];

// ---------------------------------------------------------------------------
// mma.sync / ldmatrix helpers
// ---------------------------------------------------------------------------
__device__ __forceinline__ void mma_bf16(float* d, const uint32_t* a, const uint32_t* b)
{
    asm volatile(
        "mma.sync.aligned.m16n8k16.row.col.f32.bf16.bf16.f32 "
        "{%0,%1,%2,%3}, {%4,%5,%6,%7}, {%8,%9}, {%0,%1,%2,%3};"
        : "+f"(d[0]), "+f"(d[1]), "+f"(d[2]), "+f"(d[3])
        : "r"(a[0]), "r"(a[1]), "r"(a[2]), "r"(a[3]), "r"(b[0]), "r"(b[1]));
}
__device__ __forceinline__ void mma_fp16(float* d, const uint32_t* a, const uint32_t* b)
{
    asm volatile(
        "mma.sync.aligned.m16n8k16.row.col.f32.f16.f16.f32 "
        "{%0,%1,%2,%3}, {%4,%5,%6,%7}, {%8,%9}, {%0,%1,%2,%3};"
        : "+f"(d[0]), "+f"(d[1]), "+f"(d[2]), "+f"(d[3])
        : "r"(a[0]), "r"(a[1]), "r"(a[2]), "r"(a[3]), "r"(b[0]), "r"(b[1]));
}
__device__ __forceinline__ void ldmx4(uint32_t& r0, uint32_t& r1, uint32_t& r2, uint32_t& r3,
                                      uint32_t addr)
{
    asm volatile("ldmatrix.sync.aligned.m8n8.x4.shared.b16 {%0,%1,%2,%3}, [%4];"
                 : "=r"(r0), "=r"(r1), "=r"(r2), "=r"(r3) : "r"(addr));
}
__device__ __forceinline__ void ldmx4t(uint32_t& r0, uint32_t& r1, uint32_t& r2, uint32_t& r3,
                                       uint32_t addr)
{
    asm volatile("ldmatrix.sync.aligned.m8n8.x4.trans.shared.b16 {%0,%1,%2,%3}, [%4];"
                 : "=r"(r0), "=r"(r1), "=r"(r2), "=r"(r3) : "r"(addr));
}
__device__ __forceinline__ uint32_t smem_u32(const void* p) {
    uint32_t a;
    asm("{ .reg .u64 t; cvta.to.shared.u64 t, %1; cvt.u32.u64 %0, t; }" : "=r"(a) : "l"(p));
    return a;
}
__device__ __forceinline__ uint32_t pack_bf16(float a, float b) {
    return ((uint32_t)__bfloat16_as_ushort(__float2bfloat16_rn(b)) << 16) |
            (uint32_t)__bfloat16_as_ushort(__float2bfloat16_rn(a));
}
__device__ __forceinline__ uint32_t pack_fp16(float a, float b) {
    return ((uint32_t)__half_as_ushort(__float2half_rn(b)) << 16) |
            (uint32_t)__half_as_ushort(__float2half_rn(a));
}

// ---------------------------------------------------------------------------
// Kernel 1: fused QKV projection via HMMA, bf16x3 split precision.
// CTA tile 128x192, 8 warps (2x4 -> 64x48 each), K chunks of 32, double-buffered.
// A (x) stored [row][RSTA] halves; B (W^T) stored k-major [k][RSTB] halves so
// the transposed fragment comes from ldmatrix.x4.trans and the GMEM read of W
// stays fully coalesced.
// ---------------------------------------------------------------------------
constexpr int PM = 128;
constexpr int KC = 32;
constexpr int NCH = C_ / KC;     // 12
constexpr int RSTA = 40;         // A row stride (halves)
constexpr int RSTB = 200;        // B k-row stride (halves): 192 cols + 8 pad

constexpr int AHI_OFF = 0;                         // halves
constexpr int ALO_OFF = PM * RSTA;                 // 5120
constexpr int BHI_OFF = 2 * PM * RSTA;             // 10240
constexpr int BLO_OFF = BHI_OFF + KC * RSTB;       // 16640
constexpr int BUF_HALVES = BLO_OFF + KC * RSTB;    // 23040
constexpr int SMEM_PROJ_BYTES = 2 * BUF_HALVES * 2;   // 92160

__global__ __launch_bounds__(256, 1) void proj_mma_kernel(
    const float* __restrict__ x,
    const float* __restrict__ Wq, const float* __restrict__ bq,
    const float* __restrict__ Wk, const float* __restrict__ bk,
    const float* __restrict__ Wv, const float* __restrict__ bv)
{
    extern __shared__ __align__(16) uint16_t sm[];
    const uint32_t smBase = smem_u32(sm);

    const int tid = threadIdx.x;
    const int w   = tid >> 5;
    const int l   = tid & 31;
    const int wm  = w >> 2;          // 0..1  (64-row band)
    const int wn  = w & 3;           // 0..3  (48-col band)
    const int row0 = blockIdx.x * PM;

    const int lq = l >> 2;           // 0..7
    const int lr = (l & 3) * 2;      // 0,2,4,6
    const int trow = l & 7;          // ldmatrix row within matrix
    const int tq   = l >> 3;         // ldmatrix matrix select

    float acc[4][6][4];
#pragma unroll
    for (int i = 0; i < 4; i++)
#pragma unroll
        for (int j = 0; j < 6; j++)
#pragma unroll
            for (int r = 0; r < 4; r++) acc[i][j][r] = 0.f;

    // register staging for next chunk
    float4 ra[4];
    float4 rb[6];

    auto loadA = [&](int ch) {
#pragma unroll
        for (int t = 0; t < 4; t++) {
            const int i = tid + t * 256;        // 0..1023
            const int r = i >> 3;
            const int q = i & 7;
            ra[t] = *reinterpret_cast<const float4*>(
                x + (size_t)(row0 + r) * C_ + ch * KC + q * 4);
        }
    };
    // Coalesced W load: 16 consecutive threads walk contiguous h within one k-row.
    auto loadB = [&](int ch) {
#pragma unroll
        for (int t = 0; t < 6; t++) {
            const int i   = tid + t * 256;      // 0..1535
            const int mat = i >> 9;             // 0..2
            const int rr  = i & 511;
            const int k   = rr >> 4;            // 0..31
            const int hq  = rr & 15;            // float4 along h
            const float* W = (mat == 0) ? Wq : (mat == 1) ? Wk : Wv;
            rb[t] = *reinterpret_cast<const float4*>(W + (size_t)(ch * KC + k) * H_ + hq * 4);
        }
    };
    auto cvt_store = [&](int buf) {
        uint16_t* base = sm + buf * BUF_HALVES;
        uint16_t* Ahi = base + AHI_OFF;
        uint16_t* Alo = base + ALO_OFF;
        uint16_t* Bhi = base + BHI_OFF;
        uint16_t* Blo = base + BLO_OFF;
#pragma unroll
        for (int t = 0; t < 4; t++) {
            const int i = tid + t * 256;
            const int r = i >> 3;
            const int q = i & 7;
            const float f[4] = {ra[t].x, ra[t].y, ra[t].z, ra[t].w};
            uint16_t hh[4], ll[4];
#pragma unroll
            for (int j = 0; j < 4; j++) {
                __nv_bfloat16 hb = __float2bfloat16_rn(f[j]);
                hh[j] = __bfloat16_as_ushort(hb);
                ll[j] = __bfloat16_as_ushort(__float2bfloat16_rn(f[j] - __bfloat162float(hb)));
            }
            uint2 hp, lp;
            hp.x = ((uint32_t)hh[1] << 16) | hh[0];
            hp.y = ((uint32_t)hh[3] << 16) | hh[2];
            lp.x = ((uint32_t)ll[1] << 16) | ll[0];
            lp.y = ((uint32_t)ll[3] << 16) | ll[2];
            *reinterpret_cast<uint2*>(Ahi + r * RSTA + q * 4) = hp;
            *reinterpret_cast<uint2*>(Alo + r * RSTA + q * 4) = lp;
        }
#pragma unroll
        for (int t = 0; t < 6; t++) {
            const int i   = tid + t * 256;
            const int mat = i >> 9;
            const int rr  = i & 511;
            const int k   = rr >> 4;
            const int hq  = rr & 15;
            const float f[4] = {rb[t].x, rb[t].y, rb[t].z, rb[t].w};
            uint16_t hh[4], ll[4];
#pragma unroll
            for (int j = 0; j < 4; j++) {
                __nv_bfloat16 hb = __float2bfloat16_rn(f[j]);
                hh[j] = __bfloat16_as_ushort(hb);
                ll[j] = __bfloat16_as_ushort(__float2bfloat16_rn(f[j] - __bfloat162float(hb)));
            }
            uint2 hp, lp;
            hp.x = ((uint32_t)hh[1] << 16) | hh[0];
            hp.y = ((uint32_t)hh[3] << 16) | hh[2];
            lp.x = ((uint32_t)ll[1] << 16) | ll[0];
            lp.y = ((uint32_t)ll[3] << 16) | ll[2];
            // k-major layout: row k, col = mat*64 + hq*4
            *reinterpret_cast<uint2*>(Bhi + k * RSTB + mat * 64 + hq * 4) = hp;
            *reinterpret_cast<uint2*>(Blo + k * RSTB + mat * 64 + hq * 4) = lp;
        }
    };
    auto compute = [&](int buf) {
        const uint32_t base = smBase + (uint32_t)(buf * BUF_HALVES) * 2u;
        const uint32_t aHiA = base + AHI_OFF * 2;
        const uint32_t aLoA = base + ALO_OFF * 2;
        const uint32_t bHiA = base + BHI_OFF * 2;
        const uint32_t bLoA = base + BLO_OFF * 2;
#pragma unroll
        for (int kt = 0; kt < 2; kt++) {
            uint32_t bh[6][2], bl[6][2];
#pragma unroll
            for (int jp = 0; jp < 3; jp++) {
                const int n0 = wn * 48 + jp * 16;
                const uint32_t off =
                    (uint32_t)((kt * 16 + (tq & 1) * 8 + trow) * RSTB + n0 + (tq >> 1) * 8) * 2u;
                uint32_t r0, r1, r2, r3;
                ldmx4t(r0, r1, r2, r3, bHiA + off);
                bh[jp*2][0] = r0; bh[jp*2][1] = r1;
                bh[jp*2+1][0] = r2; bh[jp*2+1][1] = r3;
                ldmx4t(r0, r1, r2, r3, bLoA + off);
                bl[jp*2][0] = r0; bl[jp*2][1] = r1;
                bl[jp*2+1][0] = r2; bl[jp*2+1][1] = r3;
            }
#pragma unroll
            for (int i = 0; i < 4; i++) {
                const int rbase = wm * 64 + i * 16;
                const uint32_t aoff =
                    (uint32_t)((rbase + (tq & 1) * 8 + trow) * RSTA + kt * 16 + (tq >> 1) * 8) * 2u;
                uint32_t a[4];
                ldmx4(a[0], a[1], a[2], a[3], aHiA + aoff);
#pragma unroll
                for (int j = 0; j < 6; j++) {
                    mma_bf16(acc[i][j], a, bh[j]);   // hi * hi
                    mma_bf16(acc[i][j], a, bl[j]);   // hi * lo
                }
                ldmx4(a[0], a[1], a[2], a[3], aLoA + aoff);
#pragma unroll
                for (int j = 0; j < 6; j++)
                    mma_bf16(acc[i][j], a, bh[j]);   // lo * hi
            }
        }
    };

    loadA(0); loadB(0);
    cvt_store(0);
    __syncthreads();
    for (int ch = 0; ch < NCH; ch++) {
        const int buf = ch & 1;
        if (ch + 1 < NCH) { loadA(ch + 1); loadB(ch + 1); }
        compute(buf);
        if (ch + 1 < NCH) cvt_store(buf ^ 1);
        __syncthreads();
    }

    // epilogue: bias + store fp32
#pragma unroll
    for (int j = 0; j < 6; j++) {
        const int n0 = wn * 48 + j * 8 + lr;
        const int mat = n0 >> 6;
        const int nn  = n0 & 63;
        float* dst = (mat == 0) ? g_q : (mat == 1) ? g_k : g_v;
        const float* bias = (mat == 0) ? bq : (mat == 1) ? bk : bv;
        const float b0 = bias[nn], b1 = bias[nn + 1];
#pragma unroll
        for (int i = 0; i < 4; i++) {
            const int r = row0 + wm * 64 + i * 16 + lq;
            float2 o0, o1;
            o0.x = acc[i][j][0] + b0;
            o0.y = acc[i][j][1] + b1;
            o1.x = acc[i][j][2] + b0;
            o1.y = acc[i][j][3] + b1;
            *reinterpret_cast<float2*>(dst + (size_t)r * H_ + nn) = o0;
            *reinterpret_cast<float2*>(dst + (size_t)(r + 8) * H_ + nn) = o1;
        }
    }
}

// ---------------------------------------------------------------------------
// Kernel 2: flash attention on mma.sync.
// QK^T: bf16 3-term split. P: fp16. V: single fp16 (lo term dropped).
// ---------------------------------------------------------------------------
constexpr int ABM = 128;
constexpr int ABN = 64;
constexpr int KVR = 72;    // padded row stride (halves)

__global__ __launch_bounds__(256, 1) void attn_mma_kernel(float* __restrict__ out)
{
    __shared__ __align__(16) uint16_t KsHi[ABN * KVR];
    __shared__ __align__(16) uint16_t KsLo[ABN * KVR];
    __shared__ __align__(16) uint16_t Vs[ABN * KVR];

    const int tid = threadIdx.x;
    const int w   = tid >> 5;
    const int l   = tid & 31;
    const int lq  = l >> 2;
    const int lr  = (l & 3) * 2;

    const int bb  = blockIdx.x;
    const int mt  = blockIdx.y;
    const int q0  = mt * ABM + w * 16;
    const size_t base = (size_t)bb * T_ * H_;

    // Q fragments (scale folded), bf16 hi/lo
    uint32_t qh[4][4], ql[4][4];
#pragma unroll
    for (int kt = 0; kt < 4; kt++) {
#pragma unroll
        for (int half = 0; half < 2; half++) {
            const int d = kt * 16 + lr + half * 8;
#pragma unroll
            for (int rh = 0; rh < 2; rh++) {
                const int r = q0 + lq + rh * 8;
                float2 v = *reinterpret_cast<const float2*>(g_q + base + (size_t)r * H_ + d);
                v.x *= SCALE_; v.y *= SCALE_;
                __nv_bfloat16 hx = __float2bfloat16_rn(v.x);
                __nv_bfloat16 hy = __float2bfloat16_rn(v.y);
                const int ri = rh + half * 2;
                qh[kt][ri] = ((uint32_t)__bfloat16_as_ushort(hy) << 16) |
                              (uint32_t)__bfloat16_as_ushort(hx);
                ql[kt][ri] = pack_bf16(v.x - __bfloat162float(hx),
                                       v.y - __bfloat162float(hy));
            }
        }
    }

    float o[8][4];
#pragma unroll
    for (int n = 0; n < 8; n++)
#pragma unroll
        for (int r = 0; r < 4; r++) o[n][r] = 0.f;
    float mrow[2] = {-1e30f, -1e30f};
    float lrow[2] = {0.f, 0.f};

    const uint32_t vsA = smem_u32(Vs);

    const int ntiles = 2 * mt + 2;
    for (int j = 0; j < ntiles; j++) {
        __syncthreads();
        // stage K (bf16 hi/lo) and V (fp16)
#pragma unroll
        for (int t = 0; t < 4; t++) {
            const int i = tid + t * 256;
            const int key = i >> 4;
            const int dq  = i & 15;
            const float4 kv = *reinterpret_cast<const float4*>(
                g_k + base + (size_t)(j * ABN + key) * H_ + dq * 4);
            const float kf[4] = {kv.x, kv.y, kv.z, kv.w};
            uint2 hp, lp;
            {
                uint16_t hh[4], ll[4];
#pragma unroll
                for (int e = 0; e < 4; e++) {
                    __nv_bfloat16 hb = __float2bfloat16_rn(kf[e]);
                    hh[e] = __bfloat16_as_ushort(hb);
                    ll[e] = __bfloat16_as_ushort(__float2bfloat16_rn(kf[e] - __bfloat162float(hb)));
                }
                hp.x = ((uint32_t)hh[1] << 16) | hh[0];
                hp.y = ((uint32_t)hh[3] << 16) | hh[2];
                lp.x = ((uint32_t)ll[1] << 16) | ll[0];
                lp.y = ((uint32_t)ll[3] << 16) | ll[2];
            }
            *reinterpret_cast<uint2*>(KsHi + key * KVR + dq * 4) = hp;
            *reinterpret_cast<uint2*>(KsLo + key * KVR + dq * 4) = lp;

            const float4 vv = *reinterpret_cast<const float4*>(
                g_v + base + (size_t)(j * ABN + key) * H_ + dq * 4);
            uint2 vp;
            vp.x = pack_fp16(vv.x, vv.y);
            vp.y = pack_fp16(vv.z, vv.w);
            *reinterpret_cast<uint2*>(Vs + key * KVR + dq * 4) = vp;
        }
        __syncthreads();

        if (j * ABN > q0 + 15) continue;   // fully masked for this warp

        // scores S[16, 64]
        float c[8][4];
#pragma unroll
        for (int nt = 0; nt < 8; nt++) {
#pragma unroll
            for (int r = 0; r < 4; r++) c[nt][r] = 0.f;
            const uint16_t* krow  = KsHi + (nt * 8 + lq) * KVR;
            const uint16_t* krowL = KsLo + (nt * 8 + lq) * KVR;
#pragma unroll
            for (int kt = 0; kt < 4; kt++) {
                uint32_t bh[2], bl[2];
                bh[0] = *reinterpret_cast<const uint32_t*>(krow + kt * 16 + lr);
                bh[1] = *reinterpret_cast<const uint32_t*>(krow + kt * 16 + lr + 8);
                bl[0] = *reinterpret_cast<const uint32_t*>(krowL + kt * 16 + lr);
                bl[1] = *reinterpret_cast<const uint32_t*>(krowL + kt * 16 + lr + 8);
                mma_bf16(c[nt], qh[kt], bh);
                mma_bf16(c[nt], qh[kt], bl);
                mma_bf16(c[nt], ql[kt], bh);
            }
        }

        // causal mask
        if ((j * ABN + ABN - 1) > q0) {
#pragma unroll
            for (int nt = 0; nt < 8; nt++) {
                const int col = j * ABN + nt * 8 + lr;
                const int r0 = q0 + lq, r1 = q0 + lq + 8;
                if (col > r0)     c[nt][0] = -1e30f;
                if (col + 1 > r0) c[nt][1] = -1e30f;
                if (col > r1)     c[nt][2] = -1e30f;
                if (col + 1 > r1) c[nt][3] = -1e30f;
            }
        }

        // online softmax
        float tm0 = -1e30f, tm1 = -1e30f;
#pragma unroll
        for (int nt = 0; nt < 8; nt++) {
            tm0 = fmaxf(tm0, fmaxf(c[nt][0], c[nt][1]));
            tm1 = fmaxf(tm1, fmaxf(c[nt][2], c[nt][3]));
        }
        tm0 = fmaxf(tm0, __shfl_xor_sync(0xffffffffu, tm0, 1));
        tm0 = fmaxf(tm0, __shfl_xor_sync(0xffffffffu, tm0, 2));
        tm1 = fmaxf(tm1, __shfl_xor_sync(0xffffffffu, tm1, 1));
        tm1 = fmaxf(tm1, __shfl_xor_sync(0xffffffffu, tm1, 2));

        const float mn0 = fmaxf(mrow[0], tm0);
        const float mn1 = fmaxf(mrow[1], tm1);
        const float corr0 = __expf(mrow[0] - mn0);
        const float corr1 = __expf(mrow[1] - mn1);
        mrow[0] = mn0; mrow[1] = mn1;

        float s0 = 0.f, s1 = 0.f;
#pragma unroll
        for (int nt = 0; nt < 8; nt++) {
            c[nt][0] = __expf(c[nt][0] - mn0);
            c[nt][1] = __expf(c[nt][1] - mn0);
            c[nt][2] = __expf(c[nt][2] - mn1);
            c[nt][3] = __expf(c[nt][3] - mn1);
            s0 += c[nt][0] + c[nt][1];
            s1 += c[nt][2] + c[nt][3];
        }
        s0 += __shfl_xor_sync(0xffffffffu, s0, 1);
        s0 += __shfl_xor_sync(0xffffffffu, s0, 2);
        s1 += __shfl_xor_sync(0xffffffffu, s1, 1);
        s1 += __shfl_xor_sync(0xffffffffu, s1, 2);
        lrow[0] = lrow[0] * corr0 + s0;
        lrow[1] = lrow[1] * corr1 + s1;

#pragma unroll
        for (int n = 0; n < 8; n++) {
            o[n][0] *= corr0; o[n][1] *= corr0;
            o[n][2] *= corr1; o[n][3] *= corr1;
        }

        // P fragments (fp16)
        uint32_t pf[4][4];
#pragma unroll
        for (int kt = 0; kt < 4; kt++) {
            pf[kt][0] = pack_fp16(c[2*kt][0],   c[2*kt][1]);
            pf[kt][1] = pack_fp16(c[2*kt][2],   c[2*kt][3]);
            pf[kt][2] = pack_fp16(c[2*kt+1][0], c[2*kt+1][1]);
            pf[kt][3] = pack_fp16(c[2*kt+1][2], c[2*kt+1][3]);
        }

        // PV: O += P * V via ldmatrix.x4.trans
        const int lm = l >> 3;
        const int lrw = l & 7;
#pragma unroll
        for (int kt = 0; kt < 4; kt++) {
#pragma unroll
            for (int dp = 0; dp < 4; dp++) {
                const uint32_t off =
                    (uint32_t)((kt * 16 + (lm & 1) * 8 + lrw) * KVR + dp * 16 + (lm >> 1) * 8) * 2u;
                uint32_t b0, b1, b2, b3;
                ldmx4t(b0, b1, b2, b3, vsA + off);
                uint32_t bA[2] = {b0, b1};
                uint32_t bB[2] = {b2, b3};
                mma_fp16(o[2*dp],     pf[kt], bA);
                mma_fp16(o[2*dp + 1], pf[kt], bB);
            }
        }
    }

    // epilogue
    const float inv0 = 1.f / lrow[0];
    const float inv1 = 1.f / lrow[1];
    const int r0 = q0 + lq, r1 = q0 + lq + 8;
#pragma unroll
    for (int nt = 0; nt < 8; nt++) {
        float2 v0, v1;
        v0.x = o[nt][0] * inv0; v0.y = o[nt][1] * inv0;
        v1.x = o[nt][2] * inv1; v1.y = o[nt][3] * inv1;
        *reinterpret_cast<float2*>(out + base + (size_t)r0 * H_ + nt * 8 + lr) = v0;
        *reinterpret_cast<float2*>(out + base + (size_t)r1 * H_ + nt * 8 + lr) = v1;
    }
}

// ---------------------------------------------------------------------------
// Launch
// ---------------------------------------------------------------------------
extern "C" void kernel_launch(void* const* d_in, const int* in_sizes, int n_in,
                              void* d_out, int out_size)
{
    const float* x  = (const float*)d_in[0];
    const float* Wq = (const float*)d_in[1];
    const float* bq = (const float*)d_in[2];
    const float* Wk = (const float*)d_in[3];
    const float* bk = (const float*)d_in[4];
    const float* Wv = (const float*)d_in[5];
    const float* bv = (const float*)d_in[6];
    float* out = (float*)d_out;

    static bool attr_set = false;
    if (!attr_set) {
        cudaFuncSetAttribute(proj_mma_kernel,
                             cudaFuncAttributeMaxDynamicSharedMemorySize, SMEM_PROJ_BYTES);
        attr_set = true;
    }

    proj_mma_kernel<<<BT_ / PM, 256, SMEM_PROJ_BYTES>>>(x, Wq, bq, Wk, bk, Wv, bv);

    dim3 grid(B_, T_ / ABM);
    attn_mma_kernel<<<grid, 256>>>(out);
}

// round 7
// speedup vs baseline: 3.1701x; 1.1241x over previous
#include <cuda_runtime.h>
#include <cuda_bf16.h>
#include <cuda_fp16.h>
#include <math.h>
#include <stdint.h>

// Problem constants
constexpr int B_ = 512;
constexpr int T_ = 256;
constexpr int C_ = 384;   // n_embd
constexpr int H_ = 64;    // head_size
constexpr int BT_ = B_ * T_;          // 131072 rows
constexpr float SCALE_ = 0.05103103630798287f;  // 384^-0.5
constexpr float QS_ = 0.05103103630798287f * 1.44269504088896341f;  // scale * log2(e)

// Packed projection outputs (32 u32 per row = 64 halves)
__device__ uint32_t g_qh[(size_t)BT_ * 32];   // bf16 hi pairs, scale*log2e folded
__device__ uint32_t g_ql[(size_t)BT_ * 32];   // bf16 lo pairs
__device__ uint32_t g_kh[(size_t)BT_ * 32];   // bf16 hi pairs
__device__ uint32_t g_kl[(size_t)BT_ * 32];   // bf16 lo pairs
__device__ uint32_t g_v16[(size_t)BT_ * 32];  // fp16 pairs

// Pre-split weights, laid out per K-chunk exactly as proj SMEM B tiles:
// [chunk 0..11][k 0..31][n 0..199 halves (192 payload + 8 pad)]
__device__ uint16_t g_wbh[12 * 32 * 200];
__device__ uint16_t g_wbl[12 * 32 * 200];

// ---------------------------------------------------------------------------
// helpers
// ---------------------------------------------------------------------------
__device__ __forceinline__ void mma_bf16(float* d, const uint32_t* a, const uint32_t* b)
{
    asm volatile(
        "mma.sync.aligned.m16n8k16.row.col.f32.bf16.bf16.f32 "
        "{%0,%1,%2,%3}, {%4,%5,%6,%7}, {%8,%9}, {%0,%1,%2,%3};"
        : "+f"(d[0]), "+f"(d[1]), "+f"(d[2]), "+f"(d[3])
        : "r"(a[0]), "r"(a[1]), "r"(a[2]), "r"(a[3]), "r"(b[0]), "r"(b[1]));
}
__device__ __forceinline__ void mma_fp16(float* d, const uint32_t* a, const uint32_t* b)
{
    asm volatile(
        "mma.sync.aligned.m16n8k16.row.col.f32.f16.f16.f32 "
        "{%0,%1,%2,%3}, {%4,%5,%6,%7}, {%8,%9}, {%0,%1,%2,%3};"
        : "+f"(d[0]), "+f"(d[1]), "+f"(d[2]), "+f"(d[3])
        : "r"(a[0]), "r"(a[1]), "r"(a[2]), "r"(a[3]), "r"(b[0]), "r"(b[1]));
}
__device__ __forceinline__ void ldmx4(uint32_t& r0, uint32_t& r1, uint32_t& r2, uint32_t& r3,
                                      uint32_t addr)
{
    asm volatile("ldmatrix.sync.aligned.m8n8.x4.shared.b16 {%0,%1,%2,%3}, [%4];"
                 : "=r"(r0), "=r"(r1), "=r"(r2), "=r"(r3) : "r"(addr));
}
__device__ __forceinline__ void ldmx4t(uint32_t& r0, uint32_t& r1, uint32_t& r2, uint32_t& r3,
                                       uint32_t addr)
{
    asm volatile("ldmatrix.sync.aligned.m8n8.x4.trans.shared.b16 {%0,%1,%2,%3}, [%4];"
                 : "=r"(r0), "=r"(r1), "=r"(r2), "=r"(r3) : "r"(addr));
}
__device__ __forceinline__ uint32_t smem_u32(const void* p) {
    uint32_t a;
    asm("{ .reg .u64 t; cvta.to.shared.u64 t, %1; cvt.u32.u64 %0, t; }" : "=r"(a) : "l"(p));
    return a;
}
__device__ __forceinline__ void cp16(uint32_t dst, const void* src) {
    asm volatile("cp.async.cg.shared.global [%0], [%1], 16;" :: "r"(dst), "l"(src) : "memory");
}
#define CP_COMMIT() asm volatile("cp.async.commit_group;" ::: "memory")
#define CP_WAIT0()  asm volatile("cp.async.wait_group 0;" ::: "memory")

__device__ __forceinline__ float ex2f(float x) {
    float r; asm("ex2.approx.f32 %0, %1;" : "=f"(r) : "f"(x)); return r;
}
__device__ __forceinline__ uint32_t pack_bf16(float a, float b) {
    return ((uint32_t)__bfloat16_as_ushort(__float2bfloat16_rn(b)) << 16) |
            (uint32_t)__bfloat16_as_ushort(__float2bfloat16_rn(a));
}
__device__ __forceinline__ uint32_t pack_fp16(float a, float b) {
    return ((uint32_t)__half_as_ushort(__float2half_rn(b)) << 16) |
            (uint32_t)__half_as_ushort(__float2half_rn(a));
}

// ---------------------------------------------------------------------------
// Kernel 0: pre-split W into bf16 hi/lo in the proj SMEM tile layout.
// ---------------------------------------------------------------------------
__global__ __launch_bounds__(256) void wsplit_kernel(
    const float* __restrict__ Wq, const float* __restrict__ Wk, const float* __restrict__ Wv)
{
    const int idx = blockIdx.x * 256 + threadIdx.x;
    if (idx >= 12 * 32 * 192) return;
    const int ch  = idx / (32 * 192);
    const int rem = idx % (32 * 192);
    const int k   = rem / 192;
    const int n   = rem % 192;
    const int mat = n >> 6, h = n & 63;
    const float* W = (mat == 0) ? Wq : (mat == 1) ? Wk : Wv;
    const float f = W[(size_t)(ch * 32 + k) * H_ + h];
    __nv_bfloat16 hb = __float2bfloat16_rn(f);
    g_wbh[ch * 6400 + k * 200 + n] = __bfloat16_as_ushort(hb);
    g_wbl[ch * 6400 + k * 200 + n] =
        __bfloat16_as_ushort(__float2bfloat16_rn(f - __bfloat162float(hb)));
}

// ---------------------------------------------------------------------------
// Kernel 1: fused QKV projection via HMMA, bf16x3 split precision.
// A staged with register cvt; B staged by cp.async from pre-split W.
// Epilogue writes packed bf16/fp16 outputs for attention.
// ---------------------------------------------------------------------------
constexpr int PM = 128;
constexpr int KC = 32;
constexpr int NCH = C_ / KC;     // 12
constexpr int RSTA = 40;
constexpr int RSTB = 200;

constexpr int AHI_OFF = 0;
constexpr int ALO_OFF = PM * RSTA;                 // 5120
constexpr int BHI_OFF = 2 * PM * RSTA;             // 10240
constexpr int BLO_OFF = BHI_OFF + KC * RSTB;       // 16640
constexpr int BUF_HALVES = BLO_OFF + KC * RSTB;    // 23040
constexpr int SMEM_PROJ_BYTES = 2 * BUF_HALVES * 2;   // 92160

__global__ __launch_bounds__(256) void proj_mma_kernel(
    const float* __restrict__ x,
    const float* __restrict__ bq, const float* __restrict__ bk, const float* __restrict__ bv)
{
    extern __shared__ __align__(16) uint16_t sm[];
    const uint32_t smBase = smem_u32(sm);

    const int tid = threadIdx.x;
    const int w   = tid >> 5;
    const int l   = tid & 31;
    const int wm  = w >> 2;
    const int wn  = w & 3;
    const int row0 = blockIdx.x * PM;

    const int lq = l >> 2;
    const int lr = (l & 3) * 2;
    const int trow = l & 7;
    const int tq   = l >> 3;

    float acc[4][6][4];
#pragma unroll
    for (int i = 0; i < 4; i++)
#pragma unroll
        for (int j = 0; j < 6; j++)
#pragma unroll
            for (int r = 0; r < 4; r++) acc[i][j][r] = 0.f;

    float4 ra[4];

    auto loadA = [&](int ch) {
#pragma unroll
        for (int t = 0; t < 4; t++) {
            const int i = tid + t * 256;
            const int r = i >> 3;
            const int q = i & 7;
            ra[t] = *reinterpret_cast<const float4*>(
                x + (size_t)(row0 + r) * C_ + ch * KC + q * 4);
        }
    };
    auto cvtA_store = [&](int buf) {
        uint16_t* Ahi = sm + buf * BUF_HALVES + AHI_OFF;
        uint16_t* Alo = sm + buf * BUF_HALVES + ALO_OFF;
#pragma unroll
        for (int t = 0; t < 4; t++) {
            const int i = tid + t * 256;
            const int r = i >> 3;
            const int q = i & 7;
            const float f[4] = {ra[t].x, ra[t].y, ra[t].z, ra[t].w};
            uint16_t hh[4], ll[4];
#pragma unroll
            for (int j = 0; j < 4; j++) {
                __nv_bfloat16 hb = __float2bfloat16_rn(f[j]);
                hh[j] = __bfloat16_as_ushort(hb);
                ll[j] = __bfloat16_as_ushort(__float2bfloat16_rn(f[j] - __bfloat162float(hb)));
            }
            uint2 hp, lp;
            hp.x = ((uint32_t)hh[1] << 16) | hh[0];
            hp.y = ((uint32_t)hh[3] << 16) | hh[2];
            lp.x = ((uint32_t)ll[1] << 16) | ll[0];
            lp.y = ((uint32_t)ll[3] << 16) | ll[2];
            *reinterpret_cast<uint2*>(Ahi + r * RSTA + q * 4) = hp;
            *reinterpret_cast<uint2*>(Alo + r * RSTA + q * 4) = lp;
        }
    };
    // B staging: pure cp.async, 3 x 16B per thread per split array
    auto copyB = [&](int ch, int buf) {
        const uint32_t dstHi = smBase + (uint32_t)(buf * BUF_HALVES + BHI_OFF) * 2u;
        const uint32_t dstLo = smBase + (uint32_t)(buf * BUF_HALVES + BLO_OFF) * 2u;
        const uint16_t* srcHi = g_wbh + ch * 6400;
        const uint16_t* srcLo = g_wbl + ch * 6400;
#pragma unroll
        for (int t = 0; t < 3; t++) {
            const int i = tid + t * 256;     // 0..767
            const int k   = i / 24;
            const int seg = i % 24;
            cp16(dstHi + (uint32_t)(k * RSTB + seg * 8) * 2u,
                 srcHi + k * 200 + seg * 8);
            cp16(dstLo + (uint32_t)(k * RSTB + seg * 8) * 2u,
                 srcLo + k * 200 + seg * 8);
        }
    };
    auto compute = [&](int buf) {
        const uint32_t base = smBase + (uint32_t)(buf * BUF_HALVES) * 2u;
        const uint32_t aHiA = base + AHI_OFF * 2;
        const uint32_t aLoA = base + ALO_OFF * 2;
        const uint32_t bHiA = base + BHI_OFF * 2;
        const uint32_t bLoA = base + BLO_OFF * 2;
#pragma unroll
        for (int kt = 0; kt < 2; kt++) {
            uint32_t bh[6][2], bl[6][2];
#pragma unroll
            for (int jp = 0; jp < 3; jp++) {
                const int n0 = wn * 48 + jp * 16;
                const uint32_t off =
                    (uint32_t)((kt * 16 + (tq & 1) * 8 + trow) * RSTB + n0 + (tq >> 1) * 8) * 2u;
                uint32_t r0, r1, r2, r3;
                ldmx4t(r0, r1, r2, r3, bHiA + off);
                bh[jp*2][0] = r0; bh[jp*2][1] = r1;
                bh[jp*2+1][0] = r2; bh[jp*2+1][1] = r3;
                ldmx4t(r0, r1, r2, r3, bLoA + off);
                bl[jp*2][0] = r0; bl[jp*2][1] = r1;
                bl[jp*2+1][0] = r2; bl[jp*2+1][1] = r3;
            }
#pragma unroll
            for (int i = 0; i < 4; i++) {
                const int rbase = wm * 64 + i * 16;
                const uint32_t aoff =
                    (uint32_t)((rbase + (tq & 1) * 8 + trow) * RSTA + kt * 16 + (tq >> 1) * 8) * 2u;
                uint32_t a[4];
                ldmx4(a[0], a[1], a[2], a[3], aHiA + aoff);
#pragma unroll
                for (int j = 0; j < 6; j++) {
                    mma_bf16(acc[i][j], a, bh[j]);   // hi*hi
                    mma_bf16(acc[i][j], a, bl[j]);   // hi*lo
                }
                ldmx4(a[0], a[1], a[2], a[3], aLoA + aoff);
#pragma unroll
                for (int j = 0; j < 6; j++)
                    mma_bf16(acc[i][j], a, bh[j]);   // lo*hi
            }
        }
    };

    // pipeline
    loadA(0);
    copyB(0, 0); CP_COMMIT();
    cvtA_store(0);
    for (int ch = 0; ch < NCH; ch++) {
        const int buf = ch & 1;
        CP_WAIT0();
        __syncthreads();
        if (ch + 1 < NCH) {
            copyB(ch + 1, buf ^ 1); CP_COMMIT();
            loadA(ch + 1);
        }
        compute(buf);
        if (ch + 1 < NCH) cvtA_store(buf ^ 1);
    }

    // epilogue: bias + pack outputs
#pragma unroll
    for (int j = 0; j < 6; j++) {
        const int n0 = wn * 48 + j * 8 + lr;
        const int mat = n0 >> 6;
        const int nn  = n0 & 63;
        const float* bias = (mat == 0) ? bq : (mat == 1) ? bk : bv;
        const float b0 = bias[nn], b1 = bias[nn + 1];
#pragma unroll
        for (int i = 0; i < 4; i++) {
            const int r = row0 + wm * 64 + i * 16 + lq;
#pragma unroll
            for (int rh = 0; rh < 2; rh++) {
                const size_t oidx = (size_t)(r + rh * 8) * 32 + nn / 2;
                float v0 = acc[i][j][rh * 2 + 0] + b0;
                float v1 = acc[i][j][rh * 2 + 1] + b1;
                if (mat == 0) {
                    v0 *= QS_; v1 *= QS_;
                    __nv_bfloat16 h0 = __float2bfloat16_rn(v0);
                    __nv_bfloat16 h1 = __float2bfloat16_rn(v1);
                    g_qh[oidx] = ((uint32_t)__bfloat16_as_ushort(h1) << 16) |
                                  (uint32_t)__bfloat16_as_ushort(h0);
                    g_ql[oidx] = pack_bf16(v0 - __bfloat162float(h0),
                                           v1 - __bfloat162float(h1));
                } else if (mat == 1) {
                    __nv_bfloat16 h0 = __float2bfloat16_rn(v0);
                    __nv_bfloat16 h1 = __float2bfloat16_rn(v1);
                    g_kh[oidx] = ((uint32_t)__bfloat16_as_ushort(h1) << 16) |
                                  (uint32_t)__bfloat16_as_ushort(h0);
                    g_kl[oidx] = pack_bf16(v0 - __bfloat162float(h0),
                                           v1 - __bfloat162float(h1));
                } else {
                    g_v16[oidx] = pack_fp16(v0, v1);
                }
            }
        }
    }
}

// ---------------------------------------------------------------------------
// Kernel 2: flash attention on mma.sync, 4 warps / 64 queries per CTA.
// K/V staged by cp.async double buffer (no conversion). Softmax in base-2.
// ---------------------------------------------------------------------------
constexpr int ABM = 64;
constexpr int ABN = 64;
constexpr int KVR = 72;
constexpr int S_KHI = 0;
constexpr int S_KLO = ABN * KVR;        // 4608 halves
constexpr int S_V   = 2 * ABN * KVR;    // 9216
constexpr int S_BUF = 3 * ABN * KVR;    // 13824 halves
constexpr int SMEM_ATTN_BYTES = 2 * S_BUF * 2;   // 55296

__global__ __launch_bounds__(128) void attn_mma_kernel(float* __restrict__ out)
{
    extern __shared__ __align__(16) uint16_t sma[];
    const uint32_t smaA = smem_u32(sma);

    const int tid = threadIdx.x;
    const int w   = tid >> 5;
    const int l   = tid & 31;
    const int lq  = l >> 2;
    const int lr  = (l & 3) * 2;

    const int bb  = blockIdx.x;
    const int mt  = blockIdx.y;
    const int q0  = mt * ABM + w * 16;
    const size_t rbase = (size_t)bb * T_;

    // Q fragments (pre-scaled, pre-split)
    uint32_t qh[4][4], ql[4][4];
    {
        const uint32_t* qhp = g_qh + rbase * 32;
        const uint32_t* qlp = g_ql + rbase * 32;
#pragma unroll
        for (int kt = 0; kt < 4; kt++)
#pragma unroll
            for (int half = 0; half < 2; half++)
#pragma unroll
                for (int rh = 0; rh < 2; rh++) {
                    const int r = q0 + lq + rh * 8;
                    const size_t idx = (size_t)r * 32 + kt * 8 + (l & 3) + half * 4;
                    qh[kt][rh + half * 2] = qhp[idx];
                    ql[kt][rh + half * 2] = qlp[idx];
                }
    }

    float o[8][4];
#pragma unroll
    for (int n = 0; n < 8; n++)
#pragma unroll
        for (int r = 0; r < 4; r++) o[n][r] = 0.f;
    float mrow[2] = {-1e30f, -1e30f};
    float lrow[2] = {0.f, 0.f};

    auto stage = [&](int j, int buf) {
        const uint32_t dst = smaA + (uint32_t)(buf * S_BUF) * 2u;
        const size_t row = rbase + (size_t)j * ABN;
#pragma unroll
        for (int t = 0; t < 4; t++) {
            const int i = tid + t * 128;     // 0..511
            const int key = i >> 3;
            const int seg = i & 7;
            const uint32_t doff = (uint32_t)(key * KVR + seg * 8) * 2u;
            cp16(dst + S_KHI * 2 + doff, g_kh + (row + key) * 32 + seg * 4);
            cp16(dst + S_KLO * 2 + doff, g_kl + (row + key) * 32 + seg * 4);
            cp16(dst + S_V * 2 + doff,   g_v16 + (row + key) * 32 + seg * 4);
        }
    };

    const int ntiles = mt + 1;
    stage(0, 0); CP_COMMIT();

    for (int j = 0; j < ntiles; j++) {
        const int buf = j & 1;
        CP_WAIT0();
        __syncthreads();
        if (j + 1 < ntiles) { stage(j + 1, buf ^ 1); CP_COMMIT(); }

        const uint16_t* Khi = sma + buf * S_BUF + S_KHI;
        const uint16_t* Klo = sma + buf * S_BUF + S_KLO;
        const uint32_t  vsA = smaA + (uint32_t)(buf * S_BUF + S_V) * 2u;

        // scores (base-2 domain; scale*log2e folded into Q)
        float c[8][4];
#pragma unroll
        for (int nt = 0; nt < 8; nt++) {
#pragma unroll
            for (int r = 0; r < 4; r++) c[nt][r] = 0.f;
            const uint16_t* krow  = Khi + (nt * 8 + lq) * KVR;
            const uint16_t* krowL = Klo + (nt * 8 + lq) * KVR;
#pragma unroll
            for (int kt = 0; kt < 4; kt++) {
                uint32_t bh[2], bl[2];
                bh[0] = *reinterpret_cast<const uint32_t*>(krow + kt * 16 + lr);
                bh[1] = *reinterpret_cast<const uint32_t*>(krow + kt * 16 + lr + 8);
                bl[0] = *reinterpret_cast<const uint32_t*>(krowL + kt * 16 + lr);
                bl[1] = *reinterpret_cast<const uint32_t*>(krowL + kt * 16 + lr + 8);
                mma_bf16(c[nt], qh[kt], bh);
                mma_bf16(c[nt], qh[kt], bl);
                mma_bf16(c[nt], ql[kt], bh);
            }
        }

        // causal mask (only last tile is partial)
        if (j == mt) {
#pragma unroll
            for (int nt = 0; nt < 8; nt++) {
                const int col = j * ABN + nt * 8 + lr;
                const int r0 = q0 + lq, r1 = q0 + lq + 8;
                if (col > r0)     c[nt][0] = -1e30f;
                if (col + 1 > r0) c[nt][1] = -1e30f;
                if (col > r1)     c[nt][2] = -1e30f;
                if (col + 1 > r1) c[nt][3] = -1e30f;
            }
        }

        // online softmax (base-2)
        float tm0 = -1e30f, tm1 = -1e30f;
#pragma unroll
        for (int nt = 0; nt < 8; nt++) {
            tm0 = fmaxf(tm0, fmaxf(c[nt][0], c[nt][1]));
            tm1 = fmaxf(tm1, fmaxf(c[nt][2], c[nt][3]));
        }
        tm0 = fmaxf(tm0, __shfl_xor_sync(0xffffffffu, tm0, 1));
        tm0 = fmaxf(tm0, __shfl_xor_sync(0xffffffffu, tm0, 2));
        tm1 = fmaxf(tm1, __shfl_xor_sync(0xffffffffu, tm1, 1));
        tm1 = fmaxf(tm1, __shfl_xor_sync(0xffffffffu, tm1, 2));

        const float mn0 = fmaxf(mrow[0], tm0);
        const float mn1 = fmaxf(mrow[1], tm1);
        const float corr0 = ex2f(mrow[0] - mn0);
        const float corr1 = ex2f(mrow[1] - mn1);
        mrow[0] = mn0; mrow[1] = mn1;

        float s0 = 0.f, s1 = 0.f;
#pragma unroll
        for (int nt = 0; nt < 8; nt++) {
            c[nt][0] = ex2f(c[nt][0] - mn0);
            c[nt][1] = ex2f(c[nt][1] - mn0);
            c[nt][2] = ex2f(c[nt][2] - mn1);
            c[nt][3] = ex2f(c[nt][3] - mn1);
            s0 += c[nt][0] + c[nt][1];
            s1 += c[nt][2] + c[nt][3];
        }
        s0 += __shfl_xor_sync(0xffffffffu, s0, 1);
        s0 += __shfl_xor_sync(0xffffffffu, s0, 2);
        s1 += __shfl_xor_sync(0xffffffffu, s1, 1);
        s1 += __shfl_xor_sync(0xffffffffu, s1, 2);
        lrow[0] = lrow[0] * corr0 + s0;
        lrow[1] = lrow[1] * corr1 + s1;

#pragma unroll
        for (int n = 0; n < 8; n++) {
            o[n][0] *= corr0; o[n][1] *= corr0;
            o[n][2] *= corr1; o[n][3] *= corr1;
        }

        // P fragments (fp16)
        uint32_t pf[4][4];
#pragma unroll
        for (int kt = 0; kt < 4; kt++) {
            pf[kt][0] = pack_fp16(c[2*kt][0],   c[2*kt][1]);
            pf[kt][1] = pack_fp16(c[2*kt][2],   c[2*kt][3]);
            pf[kt][2] = pack_fp16(c[2*kt+1][0], c[2*kt+1][1]);
            pf[kt][3] = pack_fp16(c[2*kt+1][2], c[2*kt+1][3]);
        }

        // PV
        const int lm = l >> 3;
        const int lrw = l & 7;
#pragma unroll
        for (int kt = 0; kt < 4; kt++) {
#pragma unroll
            for (int dp = 0; dp < 4; dp++) {
                const uint32_t off =
                    (uint32_t)((kt * 16 + (lm & 1) * 8 + lrw) * KVR + dp * 16 + (lm >> 1) * 8) * 2u;
                uint32_t b0, b1, b2, b3;
                ldmx4t(b0, b1, b2, b3, vsA + off);
                uint32_t bA[2] = {b0, b1};
                uint32_t bB[2] = {b2, b3};
                mma_fp16(o[2*dp],     pf[kt], bA);
                mma_fp16(o[2*dp + 1], pf[kt], bB);
            }
        }
    }

    // epilogue
    const float inv0 = 1.f / lrow[0];
    const float inv1 = 1.f / lrow[1];
    const int r0 = q0 + lq, r1 = q0 + lq + 8;
#pragma unroll
    for (int nt = 0; nt < 8; nt++) {
        float2 v0, v1;
        v0.x = o[nt][0] * inv0; v0.y = o[nt][1] * inv0;
        v1.x = o[nt][2] * inv1; v1.y = o[nt][3] * inv1;
        *reinterpret_cast<float2*>(out + (rbase + r0) * H_ + nt * 8 + lr) = v0;
        *reinterpret_cast<float2*>(out + (rbase + r1) * H_ + nt * 8 + lr) = v1;
    }
}

// ---------------------------------------------------------------------------
// Launch
// ---------------------------------------------------------------------------
extern "C" void kernel_launch(void* const* d_in, const int* in_sizes, int n_in,
                              void* d_out, int out_size)
{
    const float* x  = (const float*)d_in[0];
    const float* Wq = (const float*)d_in[1];
    const float* bq = (const float*)d_in[2];
    const float* Wk = (const float*)d_in[3];
    const float* bk = (const float*)d_in[4];
    const float* Wv = (const float*)d_in[5];
    const float* bv = (const float*)d_in[6];
    float* out = (float*)d_out;

    static bool attr_set = false;
    if (!attr_set) {
        cudaFuncSetAttribute(proj_mma_kernel,
                             cudaFuncAttributeMaxDynamicSharedMemorySize, SMEM_PROJ_BYTES);
        cudaFuncSetAttribute(attn_mma_kernel,
                             cudaFuncAttributeMaxDynamicSharedMemorySize, SMEM_ATTN_BYTES);
        attr_set = true;
    }

    wsplit_kernel<<<(12 * 32 * 192 + 255) / 256, 256>>>(Wq, Wk, Wv);
    proj_mma_kernel<<<BT_ / PM, 256, SMEM_PROJ_BYTES>>>(x, bq, bk, bv);

    dim3 grid(B_, T_ / ABM);
    attn_mma_kernel<<<grid, 128, SMEM_ATTN_BYTES>>>(out);
}

// round 11
// speedup vs baseline: 5.0924x; 1.6064x over previous
#include <cuda_runtime.h>
#include <cuda_bf16.h>
#include <cuda_fp16.h>
#include <math.h>
#include <stdint.h>

// Problem constants
constexpr int B_ = 512;
constexpr int T_ = 256;
constexpr int C_ = 384;   // n_embd
constexpr int H_ = 64;    // head_size
constexpr int BT_ = B_ * T_;          // 131072 rows
constexpr float QS_ = 0.05103103630798287f * 1.44269504088896341f;  // 384^-0.5 * log2(e)

// Packed projection outputs, fp16 pairs (32 u32 per row = 64 halves)
__device__ uint32_t g_q16[(size_t)BT_ * 32];   // Q, scale*log2e folded
__device__ uint32_t g_k16[(size_t)BT_ * 32];
__device__ uint32_t g_v16[(size_t)BT_ * 32];

// Pre-converted W (fp16), proj SMEM tile layout: [chunk][k 0..31][n 0..199]
__device__ uint16_t g_w16[12 * 32 * 200];

// ---------------------------------------------------------------------------
// helpers
// ---------------------------------------------------------------------------
__device__ __forceinline__ void mma_fp16(float* d, const uint32_t* a, const uint32_t* b)
{
    asm volatile(
        "mma.sync.aligned.m16n8k16.row.col.f32.f16.f16.f32 "
        "{%0,%1,%2,%3}, {%4,%5,%6,%7}, {%8,%9}, {%0,%1,%2,%3};"
        : "+f"(d[0]), "+f"(d[1]), "+f"(d[2]), "+f"(d[3])
        : "r"(a[0]), "r"(a[1]), "r"(a[2]), "r"(a[3]), "r"(b[0]), "r"(b[1]));
}
__device__ __forceinline__ void ldmx4(uint32_t& r0, uint32_t& r1, uint32_t& r2, uint32_t& r3,
                                      uint32_t addr)
{
    asm volatile("ldmatrix.sync.aligned.m8n8.x4.shared.b16 {%0,%1,%2,%3}, [%4];"
                 : "=r"(r0), "=r"(r1), "=r"(r2), "=r"(r3) : "r"(addr));
}
__device__ __forceinline__ void ldmx4t(uint32_t& r0, uint32_t& r1, uint32_t& r2, uint32_t& r3,
                                       uint32_t addr)
{
    asm volatile("ldmatrix.sync.aligned.m8n8.x4.trans.shared.b16 {%0,%1,%2,%3}, [%4];"
                 : "=r"(r0), "=r"(r1), "=r"(r2), "=r"(r3) : "r"(addr));
}
__device__ __forceinline__ uint32_t smem_u32(const void* p) {
    uint32_t a;
    asm("{ .reg .u64 t; cvta.to.shared.u64 t, %1; cvt.u32.u64 %0, t; }" : "=r"(a) : "l"(p));
    return a;
}
__device__ __forceinline__ void cp16(uint32_t dst, const void* src) {
    asm volatile("cp.async.cg.shared.global [%0], [%1], 16;" :: "r"(dst), "l"(src) : "memory");
}
#define CP_COMMIT() asm volatile("cp.async.commit_group;" ::: "memory")
#define CP_WAIT0()  asm volatile("cp.async.wait_group 0;" ::: "memory")

__device__ __forceinline__ float ex2f(float x) {
    float r; asm("ex2.approx.f32 %0, %1;" : "=f"(r) : "f"(x)); return r;
}
__device__ __forceinline__ uint32_t pack_fp16(float a, float b) {
    return ((uint32_t)__half_as_ushort(__float2half_rn(b)) << 16) |
            (uint32_t)__half_as_ushort(__float2half_rn(a));
}

// ---------------------------------------------------------------------------
// Kernel 0: W fp32 -> fp16, proj SMEM tile layout.
// ---------------------------------------------------------------------------
__global__ __launch_bounds__(256) void wsplit_kernel(
    const float* __restrict__ Wq, const float* __restrict__ Wk, const float* __restrict__ Wv)
{
    const int idx = blockIdx.x * 256 + threadIdx.x;
    if (idx >= 12 * 32 * 192) return;
    const int ch  = idx / (32 * 192);
    const int rem = idx % (32 * 192);
    const int k   = rem / 192;
    const int n   = rem % 192;
    const int mat = n >> 6, h = n & 63;
    const float* W = (mat == 0) ? Wq : (mat == 1) ? Wk : Wv;
    g_w16[ch * 6400 + k * 200 + n] =
        __half_as_ushort(__float2half_rn(W[(size_t)(ch * 32 + k) * H_ + h]));
}

// ---------------------------------------------------------------------------
// Kernel 1: fused QKV projection, single fp16 HMMA.
// CTA tile 128x192, 8 warps (2x4), K chunks of 32, double-buffered.
// ---------------------------------------------------------------------------
constexpr int PM = 128;
constexpr int KC = 32;
constexpr int NCH = C_ / KC;     // 12
constexpr int RSTA = 40;
constexpr int RSTB = 200;

constexpr int A_OFF = 0;
constexpr int B_OFF = PM * RSTA;                  // 5120
constexpr int BUF_HALVES = B_OFF + KC * RSTB;     // 11520

__global__ __launch_bounds__(256) void proj_mma_kernel(
    const float* __restrict__ x,
    const float* __restrict__ bq, const float* __restrict__ bk, const float* __restrict__ bv)
{
    __shared__ __align__(16) uint16_t sm[2 * BUF_HALVES];   // 46080 B
    const uint32_t smBase = smem_u32(sm);

    const int tid = threadIdx.x;
    const int w   = tid >> 5;
    const int l   = tid & 31;
    const int wm  = w >> 2;
    const int wn  = w & 3;
    const int row0 = blockIdx.x * PM;

    const int lq = l >> 2;
    const int lr = (l & 3) * 2;
    const int trow = l & 7;
    const int tq   = l >> 3;

    float acc[4][6][4];
#pragma unroll
    for (int i = 0; i < 4; i++)
#pragma unroll
        for (int j = 0; j < 6; j++)
#pragma unroll
            for (int r = 0; r < 4; r++) acc[i][j][r] = 0.f;

    float4 ra[4];

    auto loadA = [&](int ch) {
#pragma unroll
        for (int t = 0; t < 4; t++) {
            const int i = tid + t * 256;
            const int r = i >> 3;
            const int q = i & 7;
            ra[t] = *reinterpret_cast<const float4*>(
                x + (size_t)(row0 + r) * C_ + ch * KC + q * 4);
        }
    };
    auto cvtA_store = [&](int buf) {
        uint16_t* A = sm + buf * BUF_HALVES + A_OFF;
#pragma unroll
        for (int t = 0; t < 4; t++) {
            const int i = tid + t * 256;
            const int r = i >> 3;
            const int q = i & 7;
            uint2 hp;
            hp.x = pack_fp16(ra[t].x, ra[t].y);
            hp.y = pack_fp16(ra[t].z, ra[t].w);
            *reinterpret_cast<uint2*>(A + r * RSTA + q * 4) = hp;
        }
    };
    auto copyB = [&](int ch, int buf) {
        const uint32_t dst = smBase + (uint32_t)(buf * BUF_HALVES + B_OFF) * 2u;
        const uint16_t* src = g_w16 + ch * 6400;
#pragma unroll
        for (int t = 0; t < 3; t++) {
            const int i = tid + t * 256;     // 0..767
            const int k   = i / 24;
            const int seg = i % 24;
            cp16(dst + (uint32_t)(k * RSTB + seg * 8) * 2u, src + k * 200 + seg * 8);
        }
    };
    auto compute = [&](int buf) {
        const uint32_t base = smBase + (uint32_t)(buf * BUF_HALVES) * 2u;
        const uint32_t aA = base + A_OFF * 2;
        const uint32_t bA = base + B_OFF * 2;
#pragma unroll
        for (int kt = 0; kt < 2; kt++) {
            uint32_t bh[6][2];
#pragma unroll
            for (int jp = 0; jp < 3; jp++) {
                const int n0 = wn * 48 + jp * 16;
                const uint32_t off =
                    (uint32_t)((kt * 16 + (tq & 1) * 8 + trow) * RSTB + n0 + (tq >> 1) * 8) * 2u;
                uint32_t r0, r1, r2, r3;
                ldmx4t(r0, r1, r2, r3, bA + off);
                bh[jp*2][0] = r0; bh[jp*2][1] = r1;
                bh[jp*2+1][0] = r2; bh[jp*2+1][1] = r3;
            }
#pragma unroll
            for (int i = 0; i < 4; i++) {
                const int rbase = wm * 64 + i * 16;
                const uint32_t aoff =
                    (uint32_t)((rbase + (tq & 1) * 8 + trow) * RSTA + kt * 16 + (tq >> 1) * 8) * 2u;
                uint32_t a[4];
                ldmx4(a[0], a[1], a[2], a[3], aA + aoff);
#pragma unroll
                for (int j = 0; j < 6; j++)
                    mma_fp16(acc[i][j], a, bh[j]);
            }
        }
    };

    loadA(0);
    copyB(0, 0); CP_COMMIT();
    cvtA_store(0);
    for (int ch = 0; ch < NCH; ch++) {
        const int buf = ch & 1;
        CP_WAIT0();
        __syncthreads();
        if (ch + 1 < NCH) {
            copyB(ch + 1, buf ^ 1); CP_COMMIT();
            loadA(ch + 1);
        }
        compute(buf);
        if (ch + 1 < NCH) cvtA_store(buf ^ 1);
    }

    // epilogue: bias + pack fp16 outputs
#pragma unroll
    for (int j = 0; j < 6; j++) {
        const int n0 = wn * 48 + j * 8 + lr;
        const int mat = n0 >> 6;
        const int nn  = n0 & 63;
        const float* bias = (mat == 0) ? bq : (mat == 1) ? bk : bv;
        const float b0 = bias[nn], b1 = bias[nn + 1];
        uint32_t* dst = (mat == 0) ? g_q16 : (mat == 1) ? g_k16 : g_v16;
        const float s = (mat == 0) ? QS_ : 1.f;
#pragma unroll
        for (int i = 0; i < 4; i++) {
            const int r = row0 + wm * 64 + i * 16 + lq;
#pragma unroll
            for (int rh = 0; rh < 2; rh++) {
                const size_t oidx = (size_t)(r + rh * 8) * 32 + nn / 2;
                const float v0 = (acc[i][j][rh * 2 + 0] + b0) * s;
                const float v1 = (acc[i][j][rh * 2 + 1] + b1) * s;
                dst[oidx] = pack_fp16(v0, v1);
            }
        }
    }
}

// ---------------------------------------------------------------------------
// Kernel 2: flash attention, single fp16 HMMA. 4 warps / 64 queries per CTA.
// cp.async double-buffered K/V, base-2 softmax.
// ---------------------------------------------------------------------------
constexpr int ABM = 64;
constexpr int ABN = 64;
constexpr int KVR = 72;
constexpr int S_K  = 0;
constexpr int S_V  = ABN * KVR;        // 4608 halves
constexpr int S_BUF = 2 * ABN * KVR;   // 9216 halves
constexpr int SMEM_ATTN_BYTES = 2 * S_BUF * 2;   // 36864

__global__ __launch_bounds__(128) void attn_mma_kernel(float* __restrict__ out)
{
    extern __shared__ __align__(16) uint16_t sma[];
    const uint32_t smaA = smem_u32(sma);

    const int tid = threadIdx.x;
    const int w   = tid >> 5;
    const int l   = tid & 31;
    const int lq  = l >> 2;
    const int lr  = (l & 3) * 2;

    const int bb  = blockIdx.x;
    const int mt  = blockIdx.y;
    const int q0  = mt * ABM + w * 16;
    const size_t rbase = (size_t)bb * T_;

    // Q fragments (pre-scaled fp16)
    uint32_t qf[4][4];
    {
        const uint32_t* qp = g_q16 + rbase * 32;
#pragma unroll
        for (int kt = 0; kt < 4; kt++)
#pragma unroll
            for (int half = 0; half < 2; half++)
#pragma unroll
                for (int rh = 0; rh < 2; rh++) {
                    const int r = q0 + lq + rh * 8;
                    qf[kt][rh + half * 2] = qp[(size_t)r * 32 + kt * 8 + (l & 3) + half * 4];
                }
    }

    float o[8][4];
#pragma unroll
    for (int n = 0; n < 8; n++)
#pragma unroll
        for (int r = 0; r < 4; r++) o[n][r] = 0.f;
    float mrow[2] = {-1e30f, -1e30f};
    float lrow[2] = {0.f, 0.f};

    auto stage = [&](int j, int buf) {
        const uint32_t dst = smaA + (uint32_t)(buf * S_BUF) * 2u;
        const size_t row = rbase + (size_t)j * ABN;
#pragma unroll
        for (int t = 0; t < 4; t++) {
            const int i = tid + t * 128;     // 0..511
            const int key = i >> 3;
            const int seg = i & 7;
            const uint32_t doff = (uint32_t)(key * KVR + seg * 8) * 2u;
            cp16(dst + S_K * 2 + doff, g_k16 + (row + key) * 32 + seg * 4);
            cp16(dst + S_V * 2 + doff, g_v16 + (row + key) * 32 + seg * 4);
        }
    };

    const int ntiles = mt + 1;
    stage(0, 0); CP_COMMIT();

    for (int j = 0; j < ntiles; j++) {
        const int buf = j & 1;
        CP_WAIT0();
        __syncthreads();
        if (j + 1 < ntiles) { stage(j + 1, buf ^ 1); CP_COMMIT(); }

        const uint16_t* Ks = sma + buf * S_BUF + S_K;
        const uint32_t  vsA = smaA + (uint32_t)(buf * S_BUF + S_V) * 2u;

        // scores (base-2 domain)
        float c[8][4];
#pragma unroll
        for (int nt = 0; nt < 8; nt++) {
#pragma unroll
            for (int r = 0; r < 4; r++) c[nt][r] = 0.f;
            const uint16_t* krow = Ks + (nt * 8 + lq) * KVR;
#pragma unroll
            for (int kt = 0; kt < 4; kt++) {
                uint32_t bh[2];
                bh[0] = *reinterpret_cast<const uint32_t*>(krow + kt * 16 + lr);
                bh[1] = *reinterpret_cast<const uint32_t*>(krow + kt * 16 + lr + 8);
                mma_fp16(c[nt], qf[kt], bh);
            }
        }

        // causal mask (only last tile partial)
        if (j == mt) {
#pragma unroll
            for (int nt = 0; nt < 8; nt++) {
                const int col = j * ABN + nt * 8 + lr;
                const int r0 = q0 + lq, r1 = q0 + lq + 8;
                if (col > r0)     c[nt][0] = -1e30f;
                if (col + 1 > r0) c[nt][1] = -1e30f;
                if (col > r1)     c[nt][2] = -1e30f;
                if (col + 1 > r1) c[nt][3] = -1e30f;
            }
        }

        // online softmax (base-2)
        float tm0 = -1e30f, tm1 = -1e30f;
#pragma unroll
        for (int nt = 0; nt < 8; nt++) {
            tm0 = fmaxf(tm0, fmaxf(c[nt][0], c[nt][1]));
            tm1 = fmaxf(tm1, fmaxf(c[nt][2], c[nt][3]));
        }
        tm0 = fmaxf(tm0, __shfl_xor_sync(0xffffffffu, tm0, 1));
        tm0 = fmaxf(tm0, __shfl_xor_sync(0xffffffffu, tm0, 2));
        tm1 = fmaxf(tm1, __shfl_xor_sync(0xffffffffu, tm1, 1));
        tm1 = fmaxf(tm1, __shfl_xor_sync(0xffffffffu, tm1, 2));

        const float mn0 = fmaxf(mrow[0], tm0);
        const float mn1 = fmaxf(mrow[1], tm1);
        const float corr0 = ex2f(mrow[0] - mn0);
        const float corr1 = ex2f(mrow[1] - mn1);
        mrow[0] = mn0; mrow[1] = mn1;

        float s0 = 0.f, s1 = 0.f;
#pragma unroll
        for (int nt = 0; nt < 8; nt++) {
            c[nt][0] = ex2f(c[nt][0] - mn0);
            c[nt][1] = ex2f(c[nt][1] - mn0);
            c[nt][2] = ex2f(c[nt][2] - mn1);
            c[nt][3] = ex2f(c[nt][3] - mn1);
            s0 += c[nt][0] + c[nt][1];
            s1 += c[nt][2] + c[nt][3];
        }
        s0 += __shfl_xor_sync(0xffffffffu, s0, 1);
        s0 += __shfl_xor_sync(0xffffffffu, s0, 2);
        s1 += __shfl_xor_sync(0xffffffffu, s1, 1);
        s1 += __shfl_xor_sync(0xffffffffu, s1, 2);
        lrow[0] = lrow[0] * corr0 + s0;
        lrow[1] = lrow[1] * corr1 + s1;

#pragma unroll
        for (int n = 0; n < 8; n++) {
            o[n][0] *= corr0; o[n][1] *= corr0;
            o[n][2] *= corr1; o[n][3] *= corr1;
        }

        // P fragments (fp16)
        uint32_t pf[4][4];
#pragma unroll
        for (int kt = 0; kt < 4; kt++) {
            pf[kt][0] = pack_fp16(c[2*kt][0],   c[2*kt][1]);
            pf[kt][1] = pack_fp16(c[2*kt][2],   c[2*kt][3]);
            pf[kt][2] = pack_fp16(c[2*kt+1][0], c[2*kt+1][1]);
            pf[kt][3] = pack_fp16(c[2*kt+1][2], c[2*kt+1][3]);
        }

        // PV
        const int lm = l >> 3;
        const int lrw = l & 7;
#pragma unroll
        for (int kt = 0; kt < 4; kt++) {
#pragma unroll
            for (int dp = 0; dp < 4; dp++) {
                const uint32_t off =
                    (uint32_t)((kt * 16 + (lm & 1) * 8 + lrw) * KVR + dp * 16 + (lm >> 1) * 8) * 2u;
                uint32_t b0, b1, b2, b3;
                ldmx4t(b0, b1, b2, b3, vsA + off);
                uint32_t bA[2] = {b0, b1};
                uint32_t bB[2] = {b2, b3};
                mma_fp16(o[2*dp],     pf[kt], bA);
                mma_fp16(o[2*dp + 1], pf[kt], bB);
            }
        }
    }

    // epilogue
    const float inv0 = 1.f / lrow[0];
    const float inv1 = 1.f / lrow[1];
    const int r0 = q0 + lq, r1 = q0 + lq + 8;
#pragma unroll
    for (int nt = 0; nt < 8; nt++) {
        float2 v0, v1;
        v0.x = o[nt][0] * inv0; v0.y = o[nt][1] * inv0;
        v1.x = o[nt][2] * inv1; v1.y = o[nt][3] * inv1;
        *reinterpret_cast<float2*>(out + (rbase + r0) * H_ + nt * 8 + lr) = v0;
        *reinterpret_cast<float2*>(out + (rbase + r1) * H_ + nt * 8 + lr) = v1;
    }
}

// ---------------------------------------------------------------------------
// Launch
// ---------------------------------------------------------------------------
extern "C" void kernel_launch(void* const* d_in, const int* in_sizes, int n_in,
                              void* d_out, int out_size)
{
    const float* x  = (const float*)d_in[0];
    const float* Wq = (const float*)d_in[1];
    const float* bq = (const float*)d_in[2];
    const float* Wk = (const float*)d_in[3];
    const float* bk = (const float*)d_in[4];
    const float* Wv = (const float*)d_in[5];
    const float* bv = (const float*)d_in[6];
    float* out = (float*)d_out;

    static bool attr_set = false;
    if (!attr_set) {
        cudaFuncSetAttribute(attn_mma_kernel,
                             cudaFuncAttributeMaxDynamicSharedMemorySize, SMEM_ATTN_BYTES);
        attr_set = true;
    }

    wsplit_kernel<<<(12 * 32 * 192 + 255) / 256, 256>>>(Wq, Wk, Wv);
    proj_mma_kernel<<<BT_ / PM, 256>>>(x, bq, bk, bv);

    dim3 grid(B_, T_ / ABM);
    attn_mma_kernel<<<grid, 128, SMEM_ATTN_BYTES>>>(out);
}

// round 13
// speedup vs baseline: 5.1641x; 1.0141x over previous
#include <cuda_runtime.h>
#include <cuda_bf16.h>
#include <cuda_fp16.h>
#include <math.h>
#include <stdint.h>

// Problem constants
constexpr int B_ = 512;
constexpr int T_ = 256;
constexpr int C_ = 384;   // n_embd
constexpr int H_ = 64;    // head_size
constexpr int BT_ = B_ * T_;          // 131072 rows
constexpr float QS_ = 0.05103103630798287f * 1.44269504088896341f;  // 384^-0.5 * log2(e)

// Packed projection outputs, fp16 pairs (32 u32 per row = 64 halves)
__device__ uint32_t g_q16[(size_t)BT_ * 32];   // Q, scale*log2e folded
__device__ uint32_t g_k16[(size_t)BT_ * 32];
__device__ uint32_t g_v16[(size_t)BT_ * 32];

// Pre-converted W (fp16), proj SMEM tile layout: [chunk][k 0..31][n 0..199]
__device__ uint16_t g_w16[12 * 32 * 200];

// ---------------------------------------------------------------------------
// helpers
// ---------------------------------------------------------------------------
__device__ __forceinline__ void mma_fp16(float* d, const uint32_t* a, const uint32_t* b)
{
    asm volatile(
        "mma.sync.aligned.m16n8k16.row.col.f32.f16.f16.f32 "
        "{%0,%1,%2,%3}, {%4,%5,%6,%7}, {%8,%9}, {%0,%1,%2,%3};"
        : "+f"(d[0]), "+f"(d[1]), "+f"(d[2]), "+f"(d[3])
        : "r"(a[0]), "r"(a[1]), "r"(a[2]), "r"(a[3]), "r"(b[0]), "r"(b[1]));
}
__device__ __forceinline__ void ldmx4(uint32_t& r0, uint32_t& r1, uint32_t& r2, uint32_t& r3,
                                      uint32_t addr)
{
    asm volatile("ldmatrix.sync.aligned.m8n8.x4.shared.b16 {%0,%1,%2,%3}, [%4];"
                 : "=r"(r0), "=r"(r1), "=r"(r2), "=r"(r3) : "r"(addr));
}
__device__ __forceinline__ void ldmx4t(uint32_t& r0, uint32_t& r1, uint32_t& r2, uint32_t& r3,
                                       uint32_t addr)
{
    asm volatile("ldmatrix.sync.aligned.m8n8.x4.trans.shared.b16 {%0,%1,%2,%3}, [%4];"
                 : "=r"(r0), "=r"(r1), "=r"(r2), "=r"(r3) : "r"(addr));
}
__device__ __forceinline__ uint32_t smem_u32(const void* p) {
    uint32_t a;
    asm("{ .reg .u64 t; cvta.to.shared.u64 t, %1; cvt.u32.u64 %0, t; }" : "=r"(a) : "l"(p));
    return a;
}
__device__ __forceinline__ void cp16(uint32_t dst, const void* src) {
    asm volatile("cp.async.cg.shared.global [%0], [%1], 16;" :: "r"(dst), "l"(src) : "memory");
}
#define CP_COMMIT() asm volatile("cp.async.commit_group;" ::: "memory")
#define CP_WAIT0()  asm volatile("cp.async.wait_group 0;" ::: "memory")

__device__ __forceinline__ float ex2f(float x) {
    float r; asm("ex2.approx.f32 %0, %1;" : "=f"(r) : "f"(x)); return r;
}
// pack two fp32 into f16x2 (lo, hi) then exp2 both lanes
__device__ __forceinline__ uint32_t ex2_f16x2(float lo, float hi) {
    uint32_t t;
    asm("cvt.rn.f16x2.f32 %0, %1, %2;" : "=r"(t) : "f"(hi), "f"(lo));
    asm("ex2.approx.f16x2 %0, %0;" : "+r"(t));
    return t;
}
__device__ __forceinline__ uint32_t pack_fp16(float a, float b) {
    return ((uint32_t)__half_as_ushort(__float2half_rn(b)) << 16) |
            (uint32_t)__half_as_ushort(__float2half_rn(a));
}

// ---------------------------------------------------------------------------
// Kernel 0: W fp32 -> fp16, proj SMEM tile layout.
// ---------------------------------------------------------------------------
__global__ __launch_bounds__(256) void wsplit_kernel(
    const float* __restrict__ Wq, const float* __restrict__ Wk, const float* __restrict__ Wv)
{
    const int idx = blockIdx.x * 256 + threadIdx.x;
    if (idx >= 12 * 32 * 192) return;
    const int ch  = idx / (32 * 192);
    const int rem = idx % (32 * 192);
    const int k   = rem / 192;
    const int n   = rem % 192;
    const int mat = n >> 6, h = n & 63;
    const float* W = (mat == 0) ? Wq : (mat == 1) ? Wk : Wv;
    g_w16[ch * 6400 + k * 200 + n] =
        __half_as_ushort(__float2half_rn(W[(size_t)(ch * 32 + k) * H_ + h]));
}

// ---------------------------------------------------------------------------
// Kernel 1: fused QKV projection, single fp16 HMMA.
// CTA tile 128x192, 8 warps (2x4), K chunks of 32, double-buffered.
// ---------------------------------------------------------------------------
constexpr int PM = 128;
constexpr int KC = 32;
constexpr int NCH = C_ / KC;     // 12
constexpr int RSTA = 40;
constexpr int RSTB = 200;

constexpr int A_OFF = 0;
constexpr int B_OFF = PM * RSTA;                  // 5120
constexpr int BUF_HALVES = B_OFF + KC * RSTB;     // 11520

__global__ __launch_bounds__(256) void proj_mma_kernel(
    const float* __restrict__ x,
    const float* __restrict__ bq, const float* __restrict__ bk, const float* __restrict__ bv)
{
    __shared__ __align__(16) uint16_t sm[2 * BUF_HALVES];   // 46080 B
    const uint32_t smBase = smem_u32(sm);

    const int tid = threadIdx.x;
    const int w   = tid >> 5;
    const int l   = tid & 31;
    const int wm  = w >> 2;
    const int wn  = w & 3;
    const int row0 = blockIdx.x * PM;

    const int lq = l >> 2;
    const int lr = (l & 3) * 2;
    const int trow = l & 7;
    const int tq   = l >> 3;

    float acc[4][6][4];
#pragma unroll
    for (int i = 0; i < 4; i++)
#pragma unroll
        for (int j = 0; j < 6; j++)
#pragma unroll
            for (int r = 0; r < 4; r++) acc[i][j][r] = 0.f;

    float4 ra[4];

    auto loadA = [&](int ch) {
#pragma unroll
        for (int t = 0; t < 4; t++) {
            const int i = tid + t * 256;
            const int r = i >> 3;
            const int q = i & 7;
            ra[t] = *reinterpret_cast<const float4*>(
                x + (size_t)(row0 + r) * C_ + ch * KC + q * 4);
        }
    };
    auto cvtA_store = [&](int buf) {
        uint16_t* A = sm + buf * BUF_HALVES + A_OFF;
#pragma unroll
        for (int t = 0; t < 4; t++) {
            const int i = tid + t * 256;
            const int r = i >> 3;
            const int q = i & 7;
            uint2 hp;
            hp.x = pack_fp16(ra[t].x, ra[t].y);
            hp.y = pack_fp16(ra[t].z, ra[t].w);
            *reinterpret_cast<uint2*>(A + r * RSTA + q * 4) = hp;
        }
    };
    auto copyB = [&](int ch, int buf) {
        const uint32_t dst = smBase + (uint32_t)(buf * BUF_HALVES + B_OFF) * 2u;
        const uint16_t* src = g_w16 + ch * 6400;
#pragma unroll
        for (int t = 0; t < 3; t++) {
            const int i = tid + t * 256;     // 0..767
            const int k   = i / 24;
            const int seg = i % 24;
            cp16(dst + (uint32_t)(k * RSTB + seg * 8) * 2u, src + k * 200 + seg * 8);
        }
    };
    auto compute = [&](int buf) {
        const uint32_t base = smBase + (uint32_t)(buf * BUF_HALVES) * 2u;
        const uint32_t aA = base + A_OFF * 2;
        const uint32_t bA = base + B_OFF * 2;
#pragma unroll
        for (int kt = 0; kt < 2; kt++) {
            uint32_t bh[6][2];
#pragma unroll
            for (int jp = 0; jp < 3; jp++) {
                const int n0 = wn * 48 + jp * 16;
                const uint32_t off =
                    (uint32_t)((kt * 16 + (tq & 1) * 8 + trow) * RSTB + n0 + (tq >> 1) * 8) * 2u;
                uint32_t r0, r1, r2, r3;
                ldmx4t(r0, r1, r2, r3, bA + off);
                bh[jp*2][0] = r0; bh[jp*2][1] = r1;
                bh[jp*2+1][0] = r2; bh[jp*2+1][1] = r3;
            }
#pragma unroll
            for (int i = 0; i < 4; i++) {
                const int rbase = wm * 64 + i * 16;
                const uint32_t aoff =
                    (uint32_t)((rbase + (tq & 1) * 8 + trow) * RSTA + kt * 16 + (tq >> 1) * 8) * 2u;
                uint32_t a[4];
                ldmx4(a[0], a[1], a[2], a[3], aA + aoff);
#pragma unroll
                for (int j = 0; j < 6; j++)
                    mma_fp16(acc[i][j], a, bh[j]);
            }
        }
    };

    loadA(0);
    copyB(0, 0); CP_COMMIT();
    cvtA_store(0);
    for (int ch = 0; ch < NCH; ch++) {
        const int buf = ch & 1;
        CP_WAIT0();
        __syncthreads();
        if (ch + 1 < NCH) {
            copyB(ch + 1, buf ^ 1); CP_COMMIT();
            loadA(ch + 1);
        }
        compute(buf);
        if (ch + 1 < NCH) cvtA_store(buf ^ 1);
    }

    // epilogue: bias + pack fp16 outputs
#pragma unroll
    for (int j = 0; j < 6; j++) {
        const int n0 = wn * 48 + j * 8 + lr;
        const int mat = n0 >> 6;
        const int nn  = n0 & 63;
        const float* bias = (mat == 0) ? bq : (mat == 1) ? bk : bv;
        const float b0 = bias[nn], b1 = bias[nn + 1];
        uint32_t* dst = (mat == 0) ? g_q16 : (mat == 1) ? g_k16 : g_v16;
        const float s = (mat == 0) ? QS_ : 1.f;
#pragma unroll
        for (int i = 0; i < 4; i++) {
            const int r = row0 + wm * 64 + i * 16 + lq;
#pragma unroll
            for (int rh = 0; rh < 2; rh++) {
                const size_t oidx = (size_t)(r + rh * 8) * 32 + nn / 2;
                const float v0 = (acc[i][j][rh * 2 + 0] + b0) * s;
                const float v1 = (acc[i][j][rh * 2 + 1] + b1) * s;
                dst[oidx] = pack_fp16(v0, v1);
            }
        }
    }
}

// ---------------------------------------------------------------------------
// Kernel 2: flash attention, single fp16 HMMA. 4 warps / 64 queries per CTA.
// cp.async double-buffered K/V, base-2 softmax with f16x2 ex2 and ones-MMA
// row sums. Grid is (mt, b) so heavy/light CTAs interleave across waves.
// ---------------------------------------------------------------------------
constexpr int ABM = 64;
constexpr int ABN = 64;
constexpr int KVR = 72;
constexpr int S_K  = 0;
constexpr int S_V  = ABN * KVR;        // 4608 halves
constexpr int S_BUF = 2 * ABN * KVR;   // 9216 halves
constexpr int SMEM_ATTN_BYTES = 2 * S_BUF * 2;   // 36864

__global__ __launch_bounds__(128) void attn_mma_kernel(float* __restrict__ out)
{
    extern __shared__ __align__(16) uint16_t sma[];
    const uint32_t smaA = smem_u32(sma);

    const int tid = threadIdx.x;
    const int w   = tid >> 5;
    const int l   = tid & 31;
    const int lq  = l >> 2;
    const int lr  = (l & 3) * 2;

    const int mt  = blockIdx.x;          // query tile (fast dim -> wave mixing)
    const int bb  = blockIdx.y;          // batch
    const int q0  = mt * ABM + w * 16;
    const size_t rbase = (size_t)bb * T_;

    // Q fragments (pre-scaled fp16)
    uint32_t qf[4][4];
    {
        const uint32_t* qp = g_q16 + rbase * 32;
#pragma unroll
        for (int kt = 0; kt < 4; kt++)
#pragma unroll
            for (int half = 0; half < 2; half++)
#pragma unroll
                for (int rh = 0; rh < 2; rh++) {
                    const int r = q0 + lq + rh * 8;
                    qf[kt][rh + half * 2] = qp[(size_t)r * 32 + kt * 8 + (l & 3) + half * 4];
                }
    }

    float o[8][4];
#pragma unroll
    for (int n = 0; n < 8; n++)
#pragma unroll
        for (int r = 0; r < 4; r++) o[n][r] = 0.f;
    float mrow[2] = {-1e30f, -1e30f};
    float lrow[2] = {0.f, 0.f};

    auto stage = [&](int j, int buf) {
        const uint32_t dst = smaA + (uint32_t)(buf * S_BUF) * 2u;
        const size_t row = rbase + (size_t)j * ABN;
#pragma unroll
        for (int t = 0; t < 4; t++) {
            const int i = tid + t * 128;     // 0..511
            const int key = i >> 3;
            const int seg = i & 7;
            const uint32_t doff = (uint32_t)(key * KVR + seg * 8) * 2u;
            cp16(dst + S_K * 2 + doff, g_k16 + (row + key) * 32 + seg * 4);
            cp16(dst + S_V * 2 + doff, g_v16 + (row + key) * 32 + seg * 4);
        }
    };

    const int ntiles = mt + 1;
    stage(0, 0); CP_COMMIT();

    const uint32_t onesb[2] = {0x3C003C00u, 0x3C003C00u};   // f16 1.0 x4

    for (int j = 0; j < ntiles; j++) {
        const int buf = j & 1;
        CP_WAIT0();
        __syncthreads();
        if (j + 1 < ntiles) { stage(j + 1, buf ^ 1); CP_COMMIT(); }

        const uint16_t* Ks = sma + buf * S_BUF + S_K;
        const uint32_t  vsA = smaA + (uint32_t)(buf * S_BUF + S_V) * 2u;

        // scores (base-2 domain)
        float c[8][4];
#pragma unroll
        for (int nt = 0; nt < 8; nt++) {
#pragma unroll
            for (int r = 0; r < 4; r++) c[nt][r] = 0.f;
            const uint16_t* krow = Ks + (nt * 8 + lq) * KVR;
#pragma unroll
            for (int kt = 0; kt < 4; kt++) {
                uint32_t bh[2];
                bh[0] = *reinterpret_cast<const uint32_t*>(krow + kt * 16 + lr);
                bh[1] = *reinterpret_cast<const uint32_t*>(krow + kt * 16 + lr + 8);
                mma_fp16(c[nt], qf[kt], bh);
            }
        }

        // causal mask (only last tile partial)
        if (j == mt) {
#pragma unroll
            for (int nt = 0; nt < 8; nt++) {
                const int col = j * ABN + nt * 8 + lr;
                const int r0 = q0 + lq, r1 = q0 + lq + 8;
                if (col > r0)     c[nt][0] = -1e30f;
                if (col + 1 > r0) c[nt][1] = -1e30f;
                if (col > r1)     c[nt][2] = -1e30f;
                if (col + 1 > r1) c[nt][3] = -1e30f;
            }
        }

        // row max (quad reduction)
        float tm0 = -1e30f, tm1 = -1e30f;
#pragma unroll
        for (int nt = 0; nt < 8; nt++) {
            tm0 = fmaxf(tm0, fmaxf(c[nt][0], c[nt][1]));
            tm1 = fmaxf(tm1, fmaxf(c[nt][2], c[nt][3]));
        }
        tm0 = fmaxf(tm0, __shfl_xor_sync(0xffffffffu, tm0, 1));
        tm0 = fmaxf(tm0, __shfl_xor_sync(0xffffffffu, tm0, 2));
        tm1 = fmaxf(tm1, __shfl_xor_sync(0xffffffffu, tm1, 1));
        tm1 = fmaxf(tm1, __shfl_xor_sync(0xffffffffu, tm1, 2));

        const float mn0 = fmaxf(mrow[0], tm0);
        const float mn1 = fmaxf(mrow[1], tm1);
        const float corr0 = ex2f(mrow[0] - mn0);
        const float corr1 = ex2f(mrow[1] - mn1);
        mrow[0] = mn0; mrow[1] = mn1;

        // P fragments directly via f16x2 exp2 (masked -> -inf -> 0)
        uint32_t pf[4][4];
#pragma unroll
        for (int kt = 0; kt < 4; kt++) {
            pf[kt][0] = ex2_f16x2(c[2*kt][0]   - mn0, c[2*kt][1]   - mn0);
            pf[kt][1] = ex2_f16x2(c[2*kt][2]   - mn1, c[2*kt][3]   - mn1);
            pf[kt][2] = ex2_f16x2(c[2*kt+1][0] - mn0, c[2*kt+1][1] - mn0);
            pf[kt][3] = ex2_f16x2(c[2*kt+1][2] - mn1, c[2*kt+1][3] - mn1);
        }

        // row sums via ones-MMA (fp32 accum, no shuffles; consistent with fp16 P)
        float ss[4] = {0.f, 0.f, 0.f, 0.f};
#pragma unroll
        for (int kt = 0; kt < 4; kt++)
            mma_fp16(ss, pf[kt], onesb);
        lrow[0] = lrow[0] * corr0 + ss[0];
        lrow[1] = lrow[1] * corr1 + ss[2];

#pragma unroll
        for (int n = 0; n < 8; n++) {
            o[n][0] *= corr0; o[n][1] *= corr0;
            o[n][2] *= corr1; o[n][3] *= corr1;
        }

        // PV
        const int lm = l >> 3;
        const int lrw = l & 7;
#pragma unroll
        for (int kt = 0; kt < 4; kt++) {
#pragma unroll
            for (int dp = 0; dp < 4; dp++) {
                const uint32_t off =
                    (uint32_t)((kt * 16 + (lm & 1) * 8 + lrw) * KVR + dp * 16 + (lm >> 1) * 8) * 2u;
                uint32_t b0, b1, b2, b3;
                ldmx4t(b0, b1, b2, b3, vsA + off);
                uint32_t bA[2] = {b0, b1};
                uint32_t bB[2] = {b2, b3};
                mma_fp16(o[2*dp],     pf[kt], bA);
                mma_fp16(o[2*dp + 1], pf[kt], bB);
            }
        }
    }

    // epilogue
    const float inv0 = 1.f / lrow[0];
    const float inv1 = 1.f / lrow[1];
    const int r0 = q0 + lq, r1 = q0 + lq + 8;
#pragma unroll
    for (int nt = 0; nt < 8; nt++) {
        float2 v0, v1;
        v0.x = o[nt][0] * inv0; v0.y = o[nt][1] * inv0;
        v1.x = o[nt][2] * inv1; v1.y = o[nt][3] * inv1;
        *reinterpret_cast<float2*>(out + (rbase + r0) * H_ + nt * 8 + lr) = v0;
        *reinterpret_cast<float2*>(out + (rbase + r1) * H_ + nt * 8 + lr) = v1;
    }
}

// ---------------------------------------------------------------------------
// Launch
// ---------------------------------------------------------------------------
extern "C" void kernel_launch(void* const* d_in, const int* in_sizes, int n_in,
                              void* d_out, int out_size)
{
    const float* x  = (const float*)d_in[0];
    const float* Wq = (const float*)d_in[1];
    const float* bq = (const float*)d_in[2];
    const float* Wk = (const float*)d_in[3];
    const float* bk = (const float*)d_in[4];
    const float* Wv = (const float*)d_in[5];
    const float* bv = (const float*)d_in[6];
    float* out = (float*)d_out;

    static bool attr_set = false;
    if (!attr_set) {
        cudaFuncSetAttribute(attn_mma_kernel,
                             cudaFuncAttributeMaxDynamicSharedMemorySize, SMEM_ATTN_BYTES);
        attr_set = true;
    }

    wsplit_kernel<<<(12 * 32 * 192 + 255) / 256, 256>>>(Wq, Wk, Wv);
    proj_mma_kernel<<<BT_ / PM, 256>>>(x, bq, bk, bv);

    dim3 grid(T_ / ABM, B_);
    attn_mma_kernel<<<grid, 128, SMEM_ATTN_BYTES>>>(out);
}

// round 15
// speedup vs baseline: 5.7061x; 1.1050x over previous
#include <cuda_runtime.h>
#include <cuda_bf16.h>
#include <cuda_fp16.h>
#include <math.h>
#include <stdint.h>

// Problem constants
constexpr int B_ = 512;
constexpr int T_ = 256;
constexpr int C_ = 384;   // n_embd
constexpr int H_ = 64;    // head_size
constexpr int BT_ = B_ * T_;          // 131072 rows
constexpr float QS_ = 0.05103103630798287f * 1.44269504088896341f;  // 384^-0.5 * log2(e)

// Packed projection outputs, fp16 pairs (32 u32 per row = 64 halves)
__device__ uint32_t g_q16[(size_t)BT_ * 32];   // Q, scale*log2e folded
__device__ uint32_t g_k16[(size_t)BT_ * 32];
__device__ uint32_t g_v16[(size_t)BT_ * 32];

// Pre-converted W (fp16), proj SMEM tile layout: [chunk][k 0..31][n 0..199]
__device__ uint16_t g_w16[12 * 32 * 200];

// ---------------------------------------------------------------------------
// helpers
// ---------------------------------------------------------------------------
__device__ __forceinline__ void mma_fp16(float* d, const uint32_t* a, const uint32_t* b)
{
    asm volatile(
        "mma.sync.aligned.m16n8k16.row.col.f32.f16.f16.f32 "
        "{%0,%1,%2,%3}, {%4,%5,%6,%7}, {%8,%9}, {%0,%1,%2,%3};"
        : "+f"(d[0]), "+f"(d[1]), "+f"(d[2]), "+f"(d[3])
        : "r"(a[0]), "r"(a[1]), "r"(a[2]), "r"(a[3]), "r"(b[0]), "r"(b[1]));
}
__device__ __forceinline__ void ldmx4(uint32_t& r0, uint32_t& r1, uint32_t& r2, uint32_t& r3,
                                      uint32_t addr)
{
    asm volatile("ldmatrix.sync.aligned.m8n8.x4.shared.b16 {%0,%1,%2,%3}, [%4];"
                 : "=r"(r0), "=r"(r1), "=r"(r2), "=r"(r3) : "r"(addr));
}
__device__ __forceinline__ void ldmx4t(uint32_t& r0, uint32_t& r1, uint32_t& r2, uint32_t& r3,
                                       uint32_t addr)
{
    asm volatile("ldmatrix.sync.aligned.m8n8.x4.trans.shared.b16 {%0,%1,%2,%3}, [%4];"
                 : "=r"(r0), "=r"(r1), "=r"(r2), "=r"(r3) : "r"(addr));
}
__device__ __forceinline__ uint32_t smem_u32(const void* p) {
    uint32_t a;
    asm("{ .reg .u64 t; cvta.to.shared.u64 t, %1; cvt.u32.u64 %0, t; }" : "=r"(a) : "l"(p));
    return a;
}
__device__ __forceinline__ void cp16(uint32_t dst, const void* src) {
    asm volatile("cp.async.cg.shared.global [%0], [%1], 16;" :: "r"(dst), "l"(src) : "memory");
}
#define CP_COMMIT() asm volatile("cp.async.commit_group;" ::: "memory")
#define CP_WAIT0()  asm volatile("cp.async.wait_group 0;" ::: "memory")

__device__ __forceinline__ float ex2f(float x) {
    float r; asm("ex2.approx.f32 %0, %1;" : "=f"(r) : "f"(x)); return r;
}
__device__ __forceinline__ uint32_t ex2_f16x2(float lo, float hi) {
    uint32_t t;
    asm("cvt.rn.f16x2.f32 %0, %1, %2;" : "=r"(t) : "f"(hi), "f"(lo));
    asm("ex2.approx.f16x2 %0, %0;" : "+r"(t));
    return t;
}
__device__ __forceinline__ uint32_t pack_fp16(float a, float b) {
    return ((uint32_t)__half_as_ushort(__float2half_rn(b)) << 16) |
            (uint32_t)__half_as_ushort(__float2half_rn(a));
}

// ---------------------------------------------------------------------------
// Kernel 0: W fp32 -> fp16, proj SMEM tile layout.
// ---------------------------------------------------------------------------
__global__ __launch_bounds__(256) void wsplit_kernel(
    const float* __restrict__ Wq, const float* __restrict__ Wk, const float* __restrict__ Wv)
{
    const int idx = blockIdx.x * 256 + threadIdx.x;
    if (idx >= 12 * 32 * 192) return;
    const int ch  = idx / (32 * 192);
    const int rem = idx % (32 * 192);
    const int k   = rem / 192;
    const int n   = rem % 192;
    const int mat = n >> 6, h = n & 63;
    const float* W = (mat == 0) ? Wq : (mat == 1) ? Wk : Wv;
    g_w16[ch * 6400 + k * 200 + n] =
        __half_as_ushort(__float2half_rn(W[(size_t)(ch * 32 + k) * H_ + h]));
}

// ---------------------------------------------------------------------------
// Kernel 1: fused QKV projection, single fp16 HMMA.
// CTA tile 64x192 (smaller -> ~100 regs -> 2-3 CTAs/SM), 8 warps (2x4),
// K chunks of 32, double-buffered.
// ---------------------------------------------------------------------------
constexpr int PM = 64;
constexpr int KC = 32;
constexpr int NCH = C_ / KC;     // 12
constexpr int RSTA = 40;
constexpr int RSTB = 200;

constexpr int A_OFF = 0;
constexpr int B_OFF = PM * RSTA;                  // 2560
constexpr int BUF_HALVES = B_OFF + KC * RSTB;     // 8960

__global__ __launch_bounds__(256) void proj_mma_kernel(
    const float* __restrict__ x,
    const float* __restrict__ bq, const float* __restrict__ bk, const float* __restrict__ bv)
{
    __shared__ __align__(16) uint16_t sm[2 * BUF_HALVES];   // 35840 B
    const uint32_t smBase = smem_u32(sm);

    const int tid = threadIdx.x;
    const int w   = tid >> 5;
    const int l   = tid & 31;
    const int wm  = w >> 2;          // 0..1 (32-row band)
    const int wn  = w & 3;           // 0..3 (48-col band)
    const int row0 = blockIdx.x * PM;

    const int lq = l >> 2;
    const int lr = (l & 3) * 2;
    const int trow = l & 7;
    const int tq   = l >> 3;

    float acc[2][6][4];
#pragma unroll
    for (int i = 0; i < 2; i++)
#pragma unroll
        for (int j = 0; j < 6; j++)
#pragma unroll
            for (int r = 0; r < 4; r++) acc[i][j][r] = 0.f;

    float4 ra[2];

    auto loadA = [&](int ch) {
#pragma unroll
        for (int t = 0; t < 2; t++) {
            const int i = tid + t * 256;        // 0..511
            const int r = i >> 3;
            const int q = i & 7;
            ra[t] = *reinterpret_cast<const float4*>(
                x + (size_t)(row0 + r) * C_ + ch * KC + q * 4);
        }
    };
    auto cvtA_store = [&](int buf) {
        uint16_t* A = sm + buf * BUF_HALVES + A_OFF;
#pragma unroll
        for (int t = 0; t < 2; t++) {
            const int i = tid + t * 256;
            const int r = i >> 3;
            const int q = i & 7;
            uint2 hp;
            hp.x = pack_fp16(ra[t].x, ra[t].y);
            hp.y = pack_fp16(ra[t].z, ra[t].w);
            *reinterpret_cast<uint2*>(A + r * RSTA + q * 4) = hp;
        }
    };
    auto copyB = [&](int ch, int buf) {
        const uint32_t dst = smBase + (uint32_t)(buf * BUF_HALVES + B_OFF) * 2u;
        const uint16_t* src = g_w16 + ch * 6400;
#pragma unroll
        for (int t = 0; t < 3; t++) {
            const int i = tid + t * 256;     // 0..767
            const int k   = i / 24;
            const int seg = i % 24;
            cp16(dst + (uint32_t)(k * RSTB + seg * 8) * 2u, src + k * 200 + seg * 8);
        }
    };
    auto compute = [&](int buf) {
        const uint32_t base = smBase + (uint32_t)(buf * BUF_HALVES) * 2u;
        const uint32_t aA = base + A_OFF * 2;
        const uint32_t bA = base + B_OFF * 2;
#pragma unroll
        for (int kt = 0; kt < 2; kt++) {
            uint32_t bh[6][2];
#pragma unroll
            for (int jp = 0; jp < 3; jp++) {
                const int n0 = wn * 48 + jp * 16;
                const uint32_t off =
                    (uint32_t)((kt * 16 + (tq & 1) * 8 + trow) * RSTB + n0 + (tq >> 1) * 8) * 2u;
                uint32_t r0, r1, r2, r3;
                ldmx4t(r0, r1, r2, r3, bA + off);
                bh[jp*2][0] = r0; bh[jp*2][1] = r1;
                bh[jp*2+1][0] = r2; bh[jp*2+1][1] = r3;
            }
#pragma unroll
            for (int i = 0; i < 2; i++) {
                const int rbase = wm * 32 + i * 16;
                const uint32_t aoff =
                    (uint32_t)((rbase + (tq & 1) * 8 + trow) * RSTA + kt * 16 + (tq >> 1) * 8) * 2u;
                uint32_t a[4];
                ldmx4(a[0], a[1], a[2], a[3], aA + aoff);
#pragma unroll
                for (int j = 0; j < 6; j++)
                    mma_fp16(acc[i][j], a, bh[j]);
            }
        }
    };

    loadA(0);
    copyB(0, 0); CP_COMMIT();
    cvtA_store(0);
    for (int ch = 0; ch < NCH; ch++) {
        const int buf = ch & 1;
        CP_WAIT0();
        __syncthreads();
        if (ch + 1 < NCH) {
            copyB(ch + 1, buf ^ 1); CP_COMMIT();
            loadA(ch + 1);
        }
        compute(buf);
        if (ch + 1 < NCH) cvtA_store(buf ^ 1);
    }

    // epilogue: bias + pack fp16 outputs
#pragma unroll
    for (int j = 0; j < 6; j++) {
        const int n0 = wn * 48 + j * 8 + lr;
        const int mat = n0 >> 6;
        const int nn  = n0 & 63;
        const float* bias = (mat == 0) ? bq : (mat == 1) ? bk : bv;
        const float b0 = bias[nn], b1 = bias[nn + 1];
        uint32_t* dst = (mat == 0) ? g_q16 : (mat == 1) ? g_k16 : g_v16;
        const float s = (mat == 0) ? QS_ : 1.f;
#pragma unroll
        for (int i = 0; i < 2; i++) {
            const int r = row0 + wm * 32 + i * 16 + lq;
#pragma unroll
            for (int rh = 0; rh < 2; rh++) {
                const size_t oidx = (size_t)(r + rh * 8) * 32 + nn / 2;
                const float v0 = (acc[i][j][rh * 2 + 0] + b0) * s;
                const float v1 = (acc[i][j][rh * 2 + 1] + b1) * s;
                dst[oidx] = pack_fp16(v0, v1);
            }
        }
    }
}

// ---------------------------------------------------------------------------
// Kernel 2: flash attention, single fp16 HMMA. 4 warps / 64 queries per CTA.
// K fragments via ldmatrix.x4 (K row-major [key][d] == col-major B).
// cp.async double-buffered K/V, base-2 softmax, ones-MMA row sums.
// ---------------------------------------------------------------------------
constexpr int ABM = 64;
constexpr int ABN = 64;
constexpr int KVR = 72;
constexpr int S_K  = 0;
constexpr int S_V  = ABN * KVR;        // 4608 halves
constexpr int S_BUF = 2 * ABN * KVR;   // 9216 halves
constexpr int SMEM_ATTN_BYTES = 2 * S_BUF * 2;   // 36864

__global__ __launch_bounds__(128) void attn_mma_kernel(float* __restrict__ out)
{
    extern __shared__ __align__(16) uint16_t sma[];
    const uint32_t smaA = smem_u32(sma);

    const int tid = threadIdx.x;
    const int w   = tid >> 5;
    const int l   = tid & 31;
    const int lq  = l >> 2;
    const int lr  = (l & 3) * 2;

    const int mt  = blockIdx.x;          // query tile (fast dim -> wave mixing)
    const int bb  = blockIdx.y;          // batch
    const int q0  = mt * ABM + w * 16;
    const size_t rbase = (size_t)bb * T_;

    // Q fragments (pre-scaled fp16)
    uint32_t qf[4][4];
    {
        const uint32_t* qp = g_q16 + rbase * 32;
#pragma unroll
        for (int kt = 0; kt < 4; kt++)
#pragma unroll
            for (int half = 0; half < 2; half++)
#pragma unroll
                for (int rh = 0; rh < 2; rh++) {
                    const int r = q0 + lq + rh * 8;
                    qf[kt][rh + half * 2] = qp[(size_t)r * 32 + kt * 8 + (l & 3) + half * 4];
                }
    }

    float o[8][4];
#pragma unroll
    for (int n = 0; n < 8; n++)
#pragma unroll
        for (int r = 0; r < 4; r++) o[n][r] = 0.f;
    float mrow[2] = {-1e30f, -1e30f};
    float lrow[2] = {0.f, 0.f};

    auto stage = [&](int j, int buf) {
        const uint32_t dst = smaA + (uint32_t)(buf * S_BUF) * 2u;
        const size_t row = rbase + (size_t)j * ABN;
#pragma unroll
        for (int t = 0; t < 4; t++) {
            const int i = tid + t * 128;     // 0..511
            const int key = i >> 3;
            const int seg = i & 7;
            const uint32_t doff = (uint32_t)(key * KVR + seg * 8) * 2u;
            cp16(dst + S_K * 2 + doff, g_k16 + (row + key) * 32 + seg * 4);
            cp16(dst + S_V * 2 + doff, g_v16 + (row + key) * 32 + seg * 4);
        }
    };

    const int ntiles = mt + 1;
    stage(0, 0); CP_COMMIT();

    const uint32_t onesb[2] = {0x3C003C00u, 0x3C003C00u};   // f16 1.0 x4

    // ldmatrix address pieces for K b-fragments:
    // thread l -> matrix m = l>>3, row in matrix = l&7
    const int klm   = l >> 3;        // 0..3
    const int klrow = l & 7;

    for (int j = 0; j < ntiles; j++) {
        const int buf = j & 1;
        CP_WAIT0();
        __syncthreads();
        if (j + 1 < ntiles) { stage(j + 1, buf ^ 1); CP_COMMIT(); }

        const uint32_t ksA = smaA + (uint32_t)(buf * S_BUF + S_K) * 2u;
        const uint32_t vsA = smaA + (uint32_t)(buf * S_BUF + S_V) * 2u;

        // scores S[16,64] — K b-frags via ldmatrix.x4 non-trans:
        // mat0: n=p*16+0..7, k lo; mat1: n=p*16+0..7, k hi;
        // mat2: n=p*16+8..15, k lo; mat3: n=p*16+8..15, k hi
        float c[8][4];
#pragma unroll
        for (int p = 0; p < 4; p++) {        // nt pair: nt = 2p, 2p+1
            const int n_row = p * 16 + (klm >> 1) * 8 + klrow;
#pragma unroll
            for (int r = 0; r < 4; r++) { c[2*p][r] = 0.f; c[2*p+1][r] = 0.f; }
#pragma unroll
            for (int kt = 0; kt < 4; kt++) {
                const uint32_t addr = ksA +
                    (uint32_t)(n_row * KVR + kt * 16 + (klm & 1) * 8) * 2u;
                uint32_t b0, b1, b2, b3;
                ldmx4(b0, b1, b2, b3, addr);
                uint32_t bA[2] = {b0, b1};
                uint32_t bB[2] = {b2, b3};
                mma_fp16(c[2*p],     qf[kt], bA);
                mma_fp16(c[2*p + 1], qf[kt], bB);
            }
        }

        // causal mask (only last tile partial)
        if (j == mt) {
#pragma unroll
            for (int nt = 0; nt < 8; nt++) {
                const int col = j * ABN + nt * 8 + lr;
                const int r0 = q0 + lq, r1 = q0 + lq + 8;
                if (col > r0)     c[nt][0] = -1e30f;
                if (col + 1 > r0) c[nt][1] = -1e30f;
                if (col > r1)     c[nt][2] = -1e30f;
                if (col + 1 > r1) c[nt][3] = -1e30f;
            }
        }

        // row max (quad reduction)
        float tm0 = -1e30f, tm1 = -1e30f;
#pragma unroll
        for (int nt = 0; nt < 8; nt++) {
            tm0 = fmaxf(tm0, fmaxf(c[nt][0], c[nt][1]));
            tm1 = fmaxf(tm1, fmaxf(c[nt][2], c[nt][3]));
        }
        tm0 = fmaxf(tm0, __shfl_xor_sync(0xffffffffu, tm0, 1));
        tm0 = fmaxf(tm0, __shfl_xor_sync(0xffffffffu, tm0, 2));
        tm1 = fmaxf(tm1, __shfl_xor_sync(0xffffffffu, tm1, 1));
        tm1 = fmaxf(tm1, __shfl_xor_sync(0xffffffffu, tm1, 2));

        const float mn0 = fmaxf(mrow[0], tm0);
        const float mn1 = fmaxf(mrow[1], tm1);
        const float corr0 = ex2f(mrow[0] - mn0);
        const float corr1 = ex2f(mrow[1] - mn1);
        mrow[0] = mn0; mrow[1] = mn1;

        // P fragments directly via f16x2 exp2 (masked -> -inf -> 0)
        uint32_t pf[4][4];
#pragma unroll
        for (int kt = 0; kt < 4; kt++) {
            pf[kt][0] = ex2_f16x2(c[2*kt][0]   - mn0, c[2*kt][1]   - mn0);
            pf[kt][1] = ex2_f16x2(c[2*kt][2]   - mn1, c[2*kt][3]   - mn1);
            pf[kt][2] = ex2_f16x2(c[2*kt+1][0] - mn0, c[2*kt+1][1] - mn0);
            pf[kt][3] = ex2_f16x2(c[2*kt+1][2] - mn1, c[2*kt+1][3] - mn1);
        }

        // row sums via ones-MMA
        float ss[4] = {0.f, 0.f, 0.f, 0.f};
#pragma unroll
        for (int kt = 0; kt < 4; kt++)
            mma_fp16(ss, pf[kt], onesb);
        lrow[0] = lrow[0] * corr0 + ss[0];
        lrow[1] = lrow[1] * corr1 + ss[2];

#pragma unroll
        for (int n = 0; n < 8; n++) {
            o[n][0] *= corr0; o[n][1] *= corr0;
            o[n][2] *= corr1; o[n][3] *= corr1;
        }

        // PV via ldmatrix.x4.trans
#pragma unroll
        for (int kt = 0; kt < 4; kt++) {
#pragma unroll
            for (int dp = 0; dp < 4; dp++) {
                const uint32_t off =
                    (uint32_t)((kt * 16 + (klm & 1) * 8 + klrow) * KVR + dp * 16 + (klm >> 1) * 8) * 2u;
                uint32_t b0, b1, b2, b3;
                ldmx4t(b0, b1, b2, b3, vsA + off);
                uint32_t bA[2] = {b0, b1};
                uint32_t bB[2] = {b2, b3};
                mma_fp16(o[2*dp],     pf[kt], bA);
                mma_fp16(o[2*dp + 1], pf[kt], bB);
            }
        }
    }

    // epilogue
    const float inv0 = 1.f / lrow[0];
    const float inv1 = 1.f / lrow[1];
    const int r0 = q0 + lq, r1 = q0 + lq + 8;
#pragma unroll
    for (int nt = 0; nt < 8; nt++) {
        float2 v0, v1;
        v0.x = o[nt][0] * inv0; v0.y = o[nt][1] * inv0;
        v1.x = o[nt][2] * inv1; v1.y = o[nt][3] * inv1;
        *reinterpret_cast<float2*>(out + (rbase + r0) * H_ + nt * 8 + lr) = v0;
        *reinterpret_cast<float2*>(out + (rbase + r1) * H_ + nt * 8 + lr) = v1;
    }
}

// ---------------------------------------------------------------------------
// Launch
// ---------------------------------------------------------------------------
extern "C" void kernel_launch(void* const* d_in, const int* in_sizes, int n_in,
                              void* d_out, int out_size)
{
    const float* x  = (const float*)d_in[0];
    const float* Wq = (const float*)d_in[1];
    const float* bq = (const float*)d_in[2];
    const float* Wk = (const float*)d_in[3];
    const float* bk = (const float*)d_in[4];
    const float* Wv = (const float*)d_in[5];
    const float* bv = (const float*)d_in[6];
    float* out = (float*)d_out;

    static bool attr_set = false;
    if (!attr_set) {
        cudaFuncSetAttribute(attn_mma_kernel,
                             cudaFuncAttributeMaxDynamicSharedMemorySize, SMEM_ATTN_BYTES);
        attr_set = true;
    }

    wsplit_kernel<<<(12 * 32 * 192 + 255) / 256, 256>>>(Wq, Wk, Wv);
    proj_mma_kernel<<<BT_ / PM, 256>>>(x, bq, bk, bv);

    dim3 grid(T_ / ABM, B_);
    attn_mma_kernel<<<grid, 128, SMEM_ATTN_BYTES>>>(out);
}